// round 10
// baseline (speedup 1.0000x reference)
#include <cuda_runtime.h>
#include <cuda_fp16.h>
#include <stdint.h>
#include <math.h>

// Problem constants
#define BB 2
#define TT 2048
#define CC 1024
#define HH 16
#define HD 64
#define MROWS (BB*TT)

// ---------------------------------------------------------------------------
// Scratch (allocation-free rule: __device__ globals)   — all fp16 hi/lo splits
// ---------------------------------------------------------------------------
__device__ __half g_xh  [MROWS*CC];
__device__ __half g_xl  [MROWS*CC];
__device__ __half g_qkvh[3*MROWS*CC];   // [q|k|v][B,H,T,HD]
__device__ __half g_qkvl[3*MROWS*CC];
__device__ __half g_aoh [MROWS*CC];
__device__ __half g_aol [MROWS*CC];
__device__ __half g_wt  [8*CC*CC];      // [w*2+{hi,lo}][n][k]  (W^T, K-major)

// ---------------------------------------------------------------------------
// Warp-MMA helpers (base sm_80+ features)
// ---------------------------------------------------------------------------
__device__ __forceinline__ uint32_t s2u(const void* p) {
    uint32_t a;
    asm("{ .reg .u64 t; cvta.to.shared.u64 t, %1; cvt.u32.u64 %0, t; }"
        : "=r"(a) : "l"(p));
    return a;
}
__device__ __forceinline__ void ldsm_x4(uint32_t* r, uint32_t addr) {
    asm volatile("ldmatrix.sync.aligned.m8n8.x4.shared.b16 {%0,%1,%2,%3}, [%4];"
        : "=r"(r[0]), "=r"(r[1]), "=r"(r[2]), "=r"(r[3]) : "r"(addr));
}
__device__ __forceinline__ void ldsm_x4t(uint32_t* r, uint32_t addr) {
    asm volatile("ldmatrix.sync.aligned.m8n8.x4.trans.shared.b16 {%0,%1,%2,%3}, [%4];"
        : "=r"(r[0]), "=r"(r[1]), "=r"(r[2]), "=r"(r[3]) : "r"(addr));
}
// f16 inputs, f32 accumulator (main pass)
__device__ __forceinline__ void mma_f32(float* c, const uint32_t* a, const uint32_t* b) {
    asm volatile(
        "mma.sync.aligned.m16n8k16.row.col.f32.f16.f16.f32 "
        "{%0,%1,%2,%3}, {%4,%5,%6,%7}, {%8,%9}, {%0,%1,%2,%3};"
        : "+f"(c[0]), "+f"(c[1]), "+f"(c[2]), "+f"(c[3])
        : "r"(a[0]), "r"(a[1]), "r"(a[2]), "r"(a[3]), "r"(b[0]), "r"(b[1]));
}
// f16 inputs, f16 accumulator (cross-term passes)
__device__ __forceinline__ void mma_f16(uint32_t* c, const uint32_t* a, const uint32_t* b) {
    asm volatile(
        "mma.sync.aligned.m16n8k16.row.col.f16.f16.f16.f16 "
        "{%0,%1}, {%2,%3,%4,%5}, {%6,%7}, {%0,%1};"
        : "+r"(c[0]), "+r"(c[1])
        : "r"(a[0]), "r"(a[1]), "r"(a[2]), "r"(a[3]), "r"(b[0]), "r"(b[1]));
}
__device__ __forceinline__ float2 h2f(uint32_t u) {
    return __half22float2(*(__half2*)&u);
}
__device__ __forceinline__ void cpa16(uint32_t dst, const void* src) {
    asm volatile("cp.async.ca.shared.global [%0], [%1], 16;" :: "r"(dst), "l"(src));
}
#define CP_COMMIT() asm volatile("cp.async.commit_group;" ::: "memory")
#define CP_WAIT(n)  asm volatile("cp.async.wait_group %0;" :: "n"(n) : "memory")

__device__ __forceinline__ void split1(float v, __half& h, __half& l) {
    h = __float2half_rn(v);
    l = __float2half_rn(v - __half2float(h));
}
__device__ __forceinline__ uint32_t pk2(__half a, __half b) {
    __half2 t = __halves2half2(a, b);
    return *(uint32_t*)&t;
}
__device__ __forceinline__ void splitpack(float a, float b, uint32_t& hi, uint32_t& lo) {
    __half ah, al, bh, bl;
    split1(a, ah, al); split1(b, bh, bl);
    hi = pk2(ah, bh); lo = pk2(al, bl);
}

// ---------------------------------------------------------------------------
// Prep kernels
// ---------------------------------------------------------------------------
__global__ void splitx(const float* __restrict__ x,
                       __half* __restrict__ hi, __half* __restrict__ lo)
{
    const int i = blockIdx.x * blockDim.x + threadIdx.x;
    float4 v = ((const float4*)x)[i];
    __half h0,h1,h2,h3,l0,l1,l2,l3;
    split1(v.x,h0,l0); split1(v.y,h1,l1); split1(v.z,h2,l2); split1(v.w,h3,l3);
    uint2 hw = { pk2(h0,h1), pk2(h2,h3) };
    uint2 lw = { pk2(l0,l1), pk2(l2,l3) };
    ((uint2*)hi)[i] = hw;
    ((uint2*)lo)[i] = lw;
}

__global__ __launch_bounds__(256)
void wsplit4(const float* __restrict__ W0, const float* __restrict__ W1,
             const float* __restrict__ W2, const float* __restrict__ W3,
             __half* __restrict__ wt)
{
    __shared__ float t[32][33];
    const int wsel = blockIdx.z;
    const float* W = (wsel == 0) ? W0 : (wsel == 1) ? W1 : (wsel == 2) ? W2 : W3;
    __half* th = wt + (size_t)(2 * wsel)     * CC * CC;
    __half* tl = wt + (size_t)(2 * wsel + 1) * CC * CC;

    const int n0 = blockIdx.x * 32;
    const int k0 = blockIdx.y * 32;
    const int tx = threadIdx.x & 31;
    const int ty = threadIdx.x >> 5;
#pragma unroll
    for (int r = 0; r < 4; r++) {
        const int row = ty + r * 8;
        t[row][tx] = W[(size_t)(k0 + row) * CC + n0 + tx];
    }
    __syncthreads();
#pragma unroll
    for (int r = 0; r < 4; r++) {
        const int row = ty + r * 8;
        const float v = t[tx][row];
        __half h, l;
        split1(v, h, l);
        th[(size_t)(n0 + row) * CC + k0 + tx] = h;
        tl[(size_t)(n0 + row) * CC + k0 + tx] = l;
    }
}

// ---------------------------------------------------------------------------
// mma.sync split-fp16 GEMM (128x128 CTA tile, 4 stages).
// Main pass Ah*Bh in f32 acc; cross passes Ah*Bl and Al*Bh in f16 acc.
// MODE 1 (fused QKV): N=3072, fp16 hi/lo permuted out. MODE 0: fp32 out.
// ---------------------------------------------------------------------------
#define KC 16
#define TSTRIDE 48
#define TILE_B (128*TSTRIDE)
#define BUF_B  (4*TILE_B)            // 24576
#define GEMM_SMEM (4*BUF_B)          // 98304

template<int MODE>
__global__ __launch_bounds__(256, 1)
void mmagemm(const __half* __restrict__ Ah, const __half* __restrict__ Al,
             const __half* __restrict__ Wt,
             const float* __restrict__ b0, const float* __restrict__ b1,
             const float* __restrict__ b2,
             float* __restrict__ Y,
             __half* __restrict__ Yh, __half* __restrict__ Yl)
{
    extern __shared__ char dsm[];
    const uint32_t sb = s2u(dsm);

    const int tid = threadIdx.x;
    const int lane = tid & 31;
    const int wid = tid >> 5;
    const int warp_m = wid & 1;
    const int warp_n = wid >> 1;
    const int bm = blockIdx.y * 128;
    const int bn = blockIdx.x * 128;

    const int which = (MODE == 1) ? (bn >> 10) : 0;
    const int nw = bn & (CC - 1);
    const __half* Bh = Wt + (size_t)(2 * which)     * CC * CC;
    const __half* Bl = Wt + (size_t)(2 * which + 1) * CC * CC;
    const float* bias = (MODE == 0) ? b0 : (which == 0) ? b0 : (which == 1) ? b1 : b2;
    const float scale = (MODE == 1 && which == 0) ? 0.125f : 1.0f;

    float acc[4][4][4];
    uint32_t cacc[4][4][2];          // f16 cross accumulators
#pragma unroll
    for (int i = 0; i < 4; i++)
#pragma unroll
        for (int j = 0; j < 4; j++) {
#pragma unroll
            for (int q = 0; q < 4; q++) acc[i][j][q] = 0.f;
            cacc[i][j][0] = 0u; cacc[i][j][1] = 0u;
        }

    auto issue = [&](int c) {
        const int k0 = c * KC;
        const uint32_t bu = sb + (c & 3) * BUF_B;
#pragma unroll
        for (int i = 0; i < 4; i++) {
            const int j = i * 256 + tid;
            const int row = (j >> 1) & 127;
            const int seg = j & 1;
            const __half* s = (i == 0) ? Ah : (i == 1) ? Al : (i == 2) ? Bh : Bl;
            const int rb = (i < 2) ? bm : nw;
            cpa16(bu + i * TILE_B + row * TSTRIDE + seg * 16,
                  s + (size_t)(rb + row) * CC + k0 + seg * 8);
        }
        CP_COMMIT();
    };

    issue(0); issue(1); issue(2);

    const uint32_t a_off = (uint32_t)((warp_m * 64 + (lane & 15)) * TSTRIDE
                                      + (lane >> 4) * 16);
    const uint32_t b_off = (uint32_t)((warp_n * 32 + ((lane >> 4) * 8) + (lane & 7)) * TSTRIDE
                                      + ((lane >> 3) & 1) * 16);

    for (int c = 0; c < 64; c++) {
        CP_WAIT(2);
        __syncthreads();
        if (c + 3 < 64) issue(c + 3);

        const uint32_t bu = sb + (c & 3) * BUF_B;
        uint32_t af[4][4];
        uint32_t bhf[2][4], blf[2][4];

#pragma unroll
        for (int p = 0; p < 2; p++) {
            ldsm_x4(bhf[p], bu + 2*TILE_B + b_off + (uint32_t)(p * 16 * TSTRIDE));
            ldsm_x4(blf[p], bu + 3*TILE_B + b_off + (uint32_t)(p * 16 * TSTRIDE));
        }
#pragma unroll
        for (int mt = 0; mt < 4; mt++)
            ldsm_x4(af[mt], bu + a_off + (uint32_t)(mt * 16 * TSTRIDE));   // Ah
        // main: Ah*Bh (f32 acc)
#pragma unroll
        for (int mt = 0; mt < 4; mt++)
#pragma unroll
            for (int nt = 0; nt < 4; nt++)
                mma_f32(acc[mt][nt], af[mt], &bhf[nt >> 1][(nt & 1) * 2]);
        // cross: Ah*Bl (f16 acc)
#pragma unroll
        for (int mt = 0; mt < 4; mt++)
#pragma unroll
            for (int nt = 0; nt < 4; nt++)
                mma_f16(cacc[mt][nt], af[mt], &blf[nt >> 1][(nt & 1) * 2]);
#pragma unroll
        for (int mt = 0; mt < 4; mt++)
            ldsm_x4(af[mt], bu + TILE_B + a_off + (uint32_t)(mt * 16 * TSTRIDE)); // Al
        // cross: Al*Bh (f16 acc)
#pragma unroll
        for (int mt = 0; mt < 4; mt++)
#pragma unroll
            for (int nt = 0; nt < 4; nt++)
                mma_f16(cacc[mt][nt], af[mt], &bhf[nt >> 1][(nt & 1) * 2]);
    }

#pragma unroll
    for (int mt = 0; mt < 4; mt++) {
#pragma unroll
        for (int nt = 0; nt < 4; nt++) {
            const int m0 = bm + warp_m * 64 + mt * 16 + (lane >> 2);
            const int nn = nw + warp_n * 32 + nt * 8 + 2 * (lane & 3);
            const float bb0 = __ldg(bias + nn);
            const float bb1 = __ldg(bias + nn + 1);
#pragma unroll
            for (int half = 0; half < 2; half++) {
                const int m = m0 + half * 8;
                const int bb = m >> 11;
                const int tt = m & (TT - 1);
                const float2 cr = h2f(cacc[mt][nt][half]);
                const float v0 = (acc[mt][nt][half * 2 + 0] + cr.x + bb0) * scale;
                const float v1 = (acc[mt][nt][half * 2 + 1] + cr.y + bb1) * scale;
                if (MODE == 0) {
                    float2 r; r.x = v0; r.y = v1;
                    *(float2*)(Y + (size_t)m * CC + nn) = r;
                } else {
                    const int h = nn >> 6;
                    const int d = nn & (HD - 1);
                    const size_t dst = (size_t)which * MROWS * CC
                                     + (((size_t)bb * HH + h) * TT + tt) * HD + d;
                    uint32_t hw, lw;
                    splitpack(v0, v1, hw, lw);
                    *(uint32_t*)(Yh + dst) = hw;
                    *(uint32_t*)(Yl + dst) = lw;
                }
            }
        }
    }
}

// ---------------------------------------------------------------------------
// flash3: FA2-style mma.sync causal attention, split-fp16, 3-stage KV pipeline.
// Main products f32-acc, cross products f16-acc.
// CTA: 128 q-rows, 8 warps x 16 rows. KV tiles of 64 keys. 256 threads.
// ---------------------------------------------------------------------------
#define RS 144
#define QTILE_B (128*RS)
#define KVTILE_B (64*RS)
#define KVBUF_B (4*KVTILE_B)
#define FL_SMEM (2*QTILE_B + 3*KVBUF_B)

__global__ __launch_bounds__(256, 1)
void flash3(const __half* __restrict__ Qh, const __half* __restrict__ Ql,
            const __half* __restrict__ Kh, const __half* __restrict__ Kl,
            const __half* __restrict__ Vh, const __half* __restrict__ Vl)
{
    extern __shared__ char sm[];
    const uint32_t sb = s2u(sm);
    const uint32_t kvb = sb + 2 * QTILE_B;

    const int tid = threadIdx.x;
    const int lane = tid & 31;
    const int wid = tid >> 5;
    const int qt = blockIdx.x;
    const int h  = blockIdx.y;
    const int b  = blockIdx.z;
    const size_t head = ((size_t)b * HH + h) * TT * HD;

#pragma unroll
    for (int i = 0; i < 8; i++) {
        const int idx = i * 256 + tid;
        const int tile = idx >> 10;
        const int row = (idx >> 3) & 127;
        const int seg = idx & 7;
        const __half* src = (tile == 0) ? Qh : Ql;
        cpa16(sb + tile * QTILE_B + row * RS + seg * 16,
              src + head + (size_t)(qt * 128 + row) * HD + seg * 8);
    }
    CP_COMMIT();

    auto issue_kv = [&](int t) {
        const int kv0 = t * 64;
        const uint32_t bu = kvb + (t % 3) * KVBUF_B;
#pragma unroll
        for (int i = 0; i < 8; i++) {
            const int idx = i * 256 + tid;
            const int tile = idx >> 9;
            const int row = (idx >> 3) & 63;
            const int seg = idx & 7;
            const __half* src = (tile == 0) ? Kh : (tile == 1) ? Kl
                               : (tile == 2) ? Vh : Vl;
            cpa16(bu + tile * KVTILE_B + row * RS + seg * 16,
                  src + head + (size_t)(kv0 + row) * HD + seg * 8);
        }
        CP_COMMIT();
    };

    const int ntiles = (qt + 1) * 2;
    issue_kv(0);
    if (1 < ntiles) issue_kv(1);

    CP_WAIT(2);
    __syncthreads();

    uint32_t qhf[4][4], qlf[4][4];
    {
        const uint32_t qaddr = sb + (uint32_t)((wid * 16 + (lane & 15)) * RS
                                               + (lane >> 4) * 16);
#pragma unroll
        for (int ck = 0; ck < 4; ck++) {
            ldsm_x4(qhf[ck], qaddr + ck * 32);
            ldsm_x4(qlf[ck], qaddr + QTILE_B + ck * 32);
        }
    }

    float m0 = -1e30f, m1 = -1e30f, l0 = 0.f, l1 = 0.f;
    float oacc[8][4];
    uint32_t ocacc[8][2];          // f16 cross accumulators for O
#pragma unroll
    for (int nt = 0; nt < 8; nt++) {
#pragma unroll
        for (int e = 0; e < 4; e++) oacc[nt][e] = 0.f;
        ocacc[nt][0] = 0u; ocacc[nt][1] = 0u;
    }

    const int qrow = qt * 128 + wid * 16 + (lane >> 2);

    for (int t = 0; t < ntiles; t++) {
        if (t + 1 < ntiles) CP_WAIT(1);
        else                CP_WAIT(0);
        __syncthreads();
        if (t + 2 < ntiles) issue_kv(t + 2);

        const uint32_t bu = kvb + (t % 3) * KVBUF_B;

        // ---- S = Q@K^T : main f32 + cross f16 ----
        float sacc[8][4];
        uint32_t scacc[8][2];
#pragma unroll
        for (int nt = 0; nt < 8; nt++) {
#pragma unroll
            for (int e = 0; e < 4; e++) sacc[nt][e] = 0.f;
            scacc[nt][0] = 0u; scacc[nt][1] = 0u;
        }

#pragma unroll
        for (int nt = 0; nt < 8; nt++) {
            const uint32_t ka = bu + (uint32_t)((nt * 8 + (lane & 7)) * RS
                                                + (lane >> 3) * 16);
            uint32_t khf[8], klf[8];
            ldsm_x4(khf, ka);            ldsm_x4(khf + 4, ka + 64);
            ldsm_x4(klf, ka + KVTILE_B); ldsm_x4(klf + 4, ka + KVTILE_B + 64);
#pragma unroll
            for (int ck = 0; ck < 4; ck++) {
                mma_f32(sacc[nt], qhf[ck], &khf[ck * 2]);
                mma_f16(scacc[nt], qhf[ck], &klf[ck * 2]);
                mma_f16(scacc[nt], qlf[ck], &khf[ck * 2]);
            }
        }
        // merge cross terms
#pragma unroll
        for (int nt = 0; nt < 8; nt++) {
            const float2 c0 = h2f(scacc[nt][0]);
            const float2 c1 = h2f(scacc[nt][1]);
            sacc[nt][0] += c0.x; sacc[nt][1] += c0.y;
            sacc[nt][2] += c1.x; sacc[nt][3] += c1.y;
        }

        // ---- causal mask (last two tiles) ----
        if (t >= ntiles - 2) {
            const int kv0 = t * 64;
#pragma unroll
            for (int nt = 0; nt < 8; nt++)
#pragma unroll
                for (int e = 0; e < 4; e++) {
                    const int key = kv0 + nt * 8 + 2 * (lane & 3) + (e & 1);
                    const int row = qrow + ((e & 2) ? 8 : 0);
                    if (key > row) sacc[nt][e] = -1e30f;
                }
        }

        // ---- online softmax ----
#pragma unroll
        for (int hh = 0; hh < 2; hh++) {
            float& mprev = hh ? m1 : m0;
            float& lsum  = hh ? l1 : l0;
            float mx = -1e30f;
#pragma unroll
            for (int nt = 0; nt < 8; nt++)
                mx = fmaxf(mx, fmaxf(sacc[nt][hh*2], sacc[nt][hh*2+1]));
            mx = fmaxf(mx, __shfl_xor_sync(0xffffffffu, mx, 1));
            mx = fmaxf(mx, __shfl_xor_sync(0xffffffffu, mx, 2));
            const float mn = fmaxf(mprev, mx);
            const float alpha = __expf(mprev - mn);
            mprev = mn;
            float ps = 0.f;
#pragma unroll
            for (int nt = 0; nt < 8; nt++) {
                const float p0 = __expf(sacc[nt][hh*2]   - mn);
                const float p1 = __expf(sacc[nt][hh*2+1] - mn);
                ps += p0 + p1;
                sacc[nt][hh*2]   = p0;
                sacc[nt][hh*2+1] = p1;
                oacc[nt][hh*2]   *= alpha;
                oacc[nt][hh*2+1] *= alpha;
            }
            // rescale f16 cross accumulators
            const __half2 ah2 = __float2half2_rn(alpha);
#pragma unroll
            for (int nt = 0; nt < 8; nt++) {
                __half2 v = *(__half2*)&ocacc[nt][hh];
                v = __hmul2(v, ah2);
                ocacc[nt][hh] = *(uint32_t*)&v;
            }
            lsum = lsum * alpha + ps;
        }

        // ---- repack P (split hi/lo fp16) into A fragments ----
        uint32_t aph[4][4], apl[4][4];
#pragma unroll
        for (int ck = 0; ck < 4; ck++) {
            splitpack(sacc[2*ck][0],   sacc[2*ck][1],   aph[ck][0], apl[ck][0]);
            splitpack(sacc[2*ck][2],   sacc[2*ck][3],   aph[ck][1], apl[ck][1]);
            splitpack(sacc[2*ck+1][0], sacc[2*ck+1][1], aph[ck][2], apl[ck][2]);
            splitpack(sacc[2*ck+1][2], sacc[2*ck+1][3], aph[ck][3], apl[ck][3]);
        }

        // ---- O += P@V : main f32 + cross f16 ----
#pragma unroll
        for (int nt = 0; nt < 8; nt++) {
            const uint32_t va = bu + 2 * KVTILE_B + (uint32_t)(lane * RS + nt * 16);
            uint32_t vhf[8], vlf[8];
            ldsm_x4t(vhf, va);            ldsm_x4t(vhf + 4, va + 32 * RS);
            ldsm_x4t(vlf, va + KVTILE_B); ldsm_x4t(vlf + 4, va + KVTILE_B + 32 * RS);
#pragma unroll
            for (int ck = 0; ck < 4; ck++) {
                mma_f32(oacc[nt], aph[ck], &vhf[ck * 2]);
                mma_f16(ocacc[nt], aph[ck], &vlf[ck * 2]);
                mma_f16(ocacc[nt], apl[ck], &vhf[ck * 2]);
            }
        }
    }

    // ---- finalize ----
    l0 += __shfl_xor_sync(0xffffffffu, l0, 1);
    l0 += __shfl_xor_sync(0xffffffffu, l0, 2);
    l1 += __shfl_xor_sync(0xffffffffu, l1, 1);
    l1 += __shfl_xor_sync(0xffffffffu, l1, 2);
    const float inv0 = 1.f / l0;
    const float inv1 = 1.f / l1;

#pragma unroll
    for (int nt = 0; nt < 8; nt++) {
        const int d = nt * 8 + 2 * (lane & 3);
#pragma unroll
        for (int hh = 0; hh < 2; hh++) {
            const int row = qrow + hh * 8;
            const float inv = hh ? inv1 : inv0;
            const float2 cr = h2f(ocacc[nt][hh]);
            const float v0 = (oacc[nt][hh*2]   + cr.x) * inv;
            const float v1 = (oacc[nt][hh*2+1] + cr.y) * inv;
            uint32_t hw, lw;
            splitpack(v0, v1, hw, lw);
            const size_t dst = ((size_t)(b * TT + row)) * CC + h * HD + d;
            *(uint32_t*)(g_aoh + dst) = hw;
            *(uint32_t*)(g_aol + dst) = lw;
        }
    }
}

// ---------------------------------------------------------------------------
extern "C" void kernel_launch(void* const* d_in, const int* in_sizes, int n_in,
                              void* d_out, int out_size)
{
    const float* x  = (const float*)d_in[0];
    const float* Wq = (const float*)d_in[1];
    const float* bq = (const float*)d_in[2];
    const float* Wk = (const float*)d_in[3];
    const float* bk = (const float*)d_in[4];
    const float* Wv = (const float*)d_in[5];
    const float* bv = (const float*)d_in[6];
    const float* Wo = (const float*)d_in[7];
    const float* bo = (const float*)d_in[8];
    float* out = (float*)d_out;

    __half *xh, *xl, *qkvh, *qkvl, *aoh, *aol, *wt;
    cudaGetSymbolAddress((void**)&xh,   g_xh);
    cudaGetSymbolAddress((void**)&xl,   g_xl);
    cudaGetSymbolAddress((void**)&qkvh, g_qkvh);
    cudaGetSymbolAddress((void**)&qkvl, g_qkvl);
    cudaGetSymbolAddress((void**)&aoh,  g_aoh);
    cudaGetSymbolAddress((void**)&aol,  g_aol);
    cudaGetSymbolAddress((void**)&wt,   g_wt);

    static bool attr_set = false;
    if (!attr_set) {
        cudaFuncSetAttribute(mmagemm<0>, cudaFuncAttributeMaxDynamicSharedMemorySize, GEMM_SMEM);
        cudaFuncSetAttribute(mmagemm<1>, cudaFuncAttributeMaxDynamicSharedMemorySize, GEMM_SMEM);
        cudaFuncSetAttribute(flash3, cudaFuncAttributeMaxDynamicSharedMemorySize, FL_SMEM);
        attr_set = true;
    }

    const int n4 = MROWS * CC / 4;
    splitx<<<n4 / 256, 256>>>(x, xh, xl);

    dim3 wgrid(CC / 32, CC / 32, 4);
    wsplit4<<<wgrid, 256>>>(Wq, Wk, Wv, Wo, wt);

    // fused QKV projection (N = 3072)
    dim3 qkv_grid(3 * CC / 128, MROWS / 128);   // (24, 32)
    mmagemm<1><<<qkv_grid, 256, GEMM_SMEM>>>(xh, xl, wt, bq, bk, bv,
                                             nullptr, qkvh, qkvl);

    dim3 att_grid(TT / 128, HH, BB);
    flash3<<<att_grid, 256, FL_SMEM>>>(qkvh, qkvl,
                                       qkvh + (size_t)MROWS*CC, qkvl + (size_t)MROWS*CC,
                                       qkvh + 2*(size_t)MROWS*CC, qkvl + 2*(size_t)MROWS*CC);

    // output projection (N = 1024)
    dim3 out_grid(CC / 128, MROWS / 128);       // (8, 32)
    mmagemm<0><<<out_grid, 256, GEMM_SMEM>>>(aoh, aol, wt + 6*(size_t)CC*CC,
                                             bo, nullptr, nullptr,
                                             out, nullptr, nullptr);
}

// round 11
// speedup vs baseline: 1.3506x; 1.3506x over previous
#include <cuda_runtime.h>
#include <cuda_fp16.h>
#include <stdint.h>
#include <math.h>

// Problem constants
#define BB 2
#define TT 2048
#define CC 1024
#define HH 16
#define HD 64
#define MROWS (BB*TT)

// ---------------------------------------------------------------------------
// Scratch (allocation-free rule: __device__ globals)
// ---------------------------------------------------------------------------
__device__ __half g_xh [MROWS*CC];
__device__ __half g_xl [MROWS*CC];
__device__ __half g_q  [MROWS*CC];     // Q single fp16, pre-scaled, [B,H,T,HD]
__device__ __half g_kh [MROWS*CC];
__device__ __half g_kl [MROWS*CC];
__device__ __half g_vh [MROWS*CC];
__device__ __half g_vl [MROWS*CC];
__device__ __half g_ao [MROWS*CC];     // attention out single fp16, [B*T, C]
__device__ __half g_wt [8*CC*CC];      // [w*2+{hi,lo}][n][k]  (W^T, K-major)

// ---------------------------------------------------------------------------
// Warp-MMA helpers (base sm_80+ features)
// ---------------------------------------------------------------------------
__device__ __forceinline__ uint32_t s2u(const void* p) {
    uint32_t a;
    asm("{ .reg .u64 t; cvta.to.shared.u64 t, %1; cvt.u32.u64 %0, t; }"
        : "=r"(a) : "l"(p));
    return a;
}
__device__ __forceinline__ void ldsm_x4(uint32_t* r, uint32_t addr) {
    asm volatile("ldmatrix.sync.aligned.m8n8.x4.shared.b16 {%0,%1,%2,%3}, [%4];"
        : "=r"(r[0]), "=r"(r[1]), "=r"(r[2]), "=r"(r[3]) : "r"(addr));
}
__device__ __forceinline__ void ldsm_x4t(uint32_t* r, uint32_t addr) {
    asm volatile("ldmatrix.sync.aligned.m8n8.x4.trans.shared.b16 {%0,%1,%2,%3}, [%4];"
        : "=r"(r[0]), "=r"(r[1]), "=r"(r[2]), "=r"(r[3]) : "r"(addr));
}
__device__ __forceinline__ void mma_f32(float* c, const uint32_t* a, const uint32_t* b) {
    asm volatile(
        "mma.sync.aligned.m16n8k16.row.col.f32.f16.f16.f32 "
        "{%0,%1,%2,%3}, {%4,%5,%6,%7}, {%8,%9}, {%0,%1,%2,%3};"
        : "+f"(c[0]), "+f"(c[1]), "+f"(c[2]), "+f"(c[3])
        : "r"(a[0]), "r"(a[1]), "r"(a[2]), "r"(a[3]), "r"(b[0]), "r"(b[1]));
}
__device__ __forceinline__ void cpa16(uint32_t dst, const void* src) {
    asm volatile("cp.async.ca.shared.global [%0], [%1], 16;" :: "r"(dst), "l"(src));
}
#define CP_COMMIT() asm volatile("cp.async.commit_group;" ::: "memory")
#define CP_WAIT(n)  asm volatile("cp.async.wait_group %0;" :: "n"(n) : "memory")

__device__ __forceinline__ void split1(float v, __half& h, __half& l) {
    h = __float2half_rn(v);
    l = __float2half_rn(v - __half2float(h));
}
__device__ __forceinline__ uint32_t pk2(__half a, __half b) {
    __half2 t = __halves2half2(a, b);
    return *(uint32_t*)&t;
}
__device__ __forceinline__ uint32_t pkf2(float a, float b) {
    __half2 t = __floats2half2_rn(a, b);
    return *(uint32_t*)&t;
}
__device__ __forceinline__ void splitpack(float a, float b, uint32_t& hi, uint32_t& lo) {
    __half ah, al, bh, bl;
    split1(a, ah, al); split1(b, bh, bl);
    hi = pk2(ah, bh); lo = pk2(al, bl);
}

// ---------------------------------------------------------------------------
// Prep kernels
// ---------------------------------------------------------------------------
__global__ void splitx(const float* __restrict__ x,
                       __half* __restrict__ hi, __half* __restrict__ lo)
{
    const int i = blockIdx.x * blockDim.x + threadIdx.x;
    float4 v = ((const float4*)x)[i];
    __half h0,h1,h2,h3,l0,l1,l2,l3;
    split1(v.x,h0,l0); split1(v.y,h1,l1); split1(v.z,h2,l2); split1(v.w,h3,l3);
    uint2 hw = { pk2(h0,h1), pk2(h2,h3) };
    uint2 lw = { pk2(l0,l1), pk2(l2,l3) };
    ((uint2*)hi)[i] = hw;
    ((uint2*)lo)[i] = lw;
}

__global__ __launch_bounds__(256)
void wsplit4(const float* __restrict__ W0, const float* __restrict__ W1,
             const float* __restrict__ W2, const float* __restrict__ W3,
             __half* __restrict__ wt)
{
    __shared__ float t[32][33];
    const int wsel = blockIdx.z;
    const float* W = (wsel == 0) ? W0 : (wsel == 1) ? W1 : (wsel == 2) ? W2 : W3;
    __half* th = wt + (size_t)(2 * wsel)     * CC * CC;
    __half* tl = wt + (size_t)(2 * wsel + 1) * CC * CC;

    const int n0 = blockIdx.x * 32;
    const int k0 = blockIdx.y * 32;
    const int tx = threadIdx.x & 31;
    const int ty = threadIdx.x >> 5;
#pragma unroll
    for (int r = 0; r < 4; r++) {
        const int row = ty + r * 8;
        t[row][tx] = W[(size_t)(k0 + row) * CC + n0 + tx];
    }
    __syncthreads();
#pragma unroll
    for (int r = 0; r < 4; r++) {
        const int row = ty + r * 8;
        const float v = t[tx][row];
        __half h, l;
        split1(v, h, l);
        th[(size_t)(n0 + row) * CC + k0 + tx] = h;
        tl[(size_t)(n0 + row) * CC + k0 + tx] = l;
    }
}

// ---------------------------------------------------------------------------
// mma.sync split-fp16 GEMM (128x128 CTA tile, 4 stages, all f32-acc).
// PASSES=3: Ah*Bh + Ah*Bl + Al*Bh.   PASSES=2: Ah*Bh + Ah*Bl (A single).
// MODE 1 (fused QKV, PASSES=3): N=3072; Q -> single fp16 scaled; K,V -> split.
// MODE 0 (out proj, PASSES=2):  N=1024; fp32 out.
// ---------------------------------------------------------------------------
#define KC 16
#define TSTRIDE 48
#define TILE_B (128*TSTRIDE)
#define BUF_B  (4*TILE_B)            // 24576
#define GEMM_SMEM (4*BUF_B)          // 98304

template<int MODE, int PASSES>
__global__ __launch_bounds__(256, 2)
void mmagemm(const __half* __restrict__ Ah, const __half* __restrict__ Al,
             const __half* __restrict__ Wt,
             const float* __restrict__ b0, const float* __restrict__ b1,
             const float* __restrict__ b2,
             float* __restrict__ Y,
             __half* __restrict__ Yq,
             __half* __restrict__ Ykh, __half* __restrict__ Ykl,
             __half* __restrict__ Yvh, __half* __restrict__ Yvl)
{
    extern __shared__ char dsm[];
    const uint32_t sb = s2u(dsm);

    const int tid = threadIdx.x;
    const int lane = tid & 31;
    const int wid = tid >> 5;
    const int warp_m = wid & 1;
    const int warp_n = wid >> 1;
    const int bm = blockIdx.y * 128;
    const int bn = blockIdx.x * 128;

    const int which = (MODE == 1) ? (bn >> 10) : 0;
    const int nw = bn & (CC - 1);
    const __half* Bh = Wt + (size_t)(2 * which)     * CC * CC;
    const __half* Bl = Wt + (size_t)(2 * which + 1) * CC * CC;
    const float* bias = (MODE == 0) ? b0 : (which == 0) ? b0 : (which == 1) ? b1 : b2;
    const float scale = (MODE == 1 && which == 0) ? 0.125f : 1.0f;

    float acc[4][4][4];
#pragma unroll
    for (int i = 0; i < 4; i++)
#pragma unroll
        for (int j = 0; j < 4; j++)
#pragma unroll
            for (int q = 0; q < 4; q++) acc[i][j][q] = 0.f;

    auto issue = [&](int c) {
        const int k0 = c * KC;
        const uint32_t bu = sb + (c & 3) * BUF_B;
#pragma unroll
        for (int i = 0; i < 4; i++) {
            if (PASSES == 2 && i == 1) continue;   // no Al tile needed
            const int j = i * 256 + tid;
            const int row = (j >> 1) & 127;
            const int seg = j & 1;
            const __half* s = (i == 0) ? Ah : (i == 1) ? Al : (i == 2) ? Bh : Bl;
            const int rb = (i < 2) ? bm : nw;
            cpa16(bu + i * TILE_B + row * TSTRIDE + seg * 16,
                  s + (size_t)(rb + row) * CC + k0 + seg * 8);
        }
        CP_COMMIT();
    };

    issue(0); issue(1); issue(2);

    const uint32_t a_off = (uint32_t)((warp_m * 64 + (lane & 15)) * TSTRIDE
                                      + (lane >> 4) * 16);
    const uint32_t b_off = (uint32_t)((warp_n * 32 + ((lane >> 4) * 8) + (lane & 7)) * TSTRIDE
                                      + ((lane >> 3) & 1) * 16);

    for (int c = 0; c < 64; c++) {
        CP_WAIT(2);
        __syncthreads();
        if (c + 3 < 64) issue(c + 3);

        const uint32_t bu = sb + (c & 3) * BUF_B;
        uint32_t af[4][4];
        uint32_t bhf[2][4], blf[2][4];

#pragma unroll
        for (int p = 0; p < 2; p++) {
            ldsm_x4(bhf[p], bu + 2*TILE_B + b_off + (uint32_t)(p * 16 * TSTRIDE));
            ldsm_x4(blf[p], bu + 3*TILE_B + b_off + (uint32_t)(p * 16 * TSTRIDE));
        }
#pragma unroll
        for (int mt = 0; mt < 4; mt++)
            ldsm_x4(af[mt], bu + a_off + (uint32_t)(mt * 16 * TSTRIDE));   // Ah
        // pass 1: Ah*Bh
#pragma unroll
        for (int mt = 0; mt < 4; mt++)
#pragma unroll
            for (int nt = 0; nt < 4; nt++)
                mma_f32(acc[mt][nt], af[mt], &bhf[nt >> 1][(nt & 1) * 2]);
        // pass 2: Ah*Bl
#pragma unroll
        for (int mt = 0; mt < 4; mt++)
#pragma unroll
            for (int nt = 0; nt < 4; nt++)
                mma_f32(acc[mt][nt], af[mt], &blf[nt >> 1][(nt & 1) * 2]);
        if (PASSES == 3) {
            // pass 3: Al*Bh
#pragma unroll
            for (int mt = 0; mt < 4; mt++)
                ldsm_x4(af[mt], bu + TILE_B + a_off + (uint32_t)(mt * 16 * TSTRIDE));
#pragma unroll
            for (int mt = 0; mt < 4; mt++)
#pragma unroll
                for (int nt = 0; nt < 4; nt++)
                    mma_f32(acc[mt][nt], af[mt], &bhf[nt >> 1][(nt & 1) * 2]);
        }
    }

#pragma unroll
    for (int mt = 0; mt < 4; mt++) {
#pragma unroll
        for (int nt = 0; nt < 4; nt++) {
            const int m0 = bm + warp_m * 64 + mt * 16 + (lane >> 2);
            const int nn = nw + warp_n * 32 + nt * 8 + 2 * (lane & 3);
            const float bb0 = __ldg(bias + nn);
            const float bb1 = __ldg(bias + nn + 1);
#pragma unroll
            for (int half = 0; half < 2; half++) {
                const int m = m0 + half * 8;
                const int bb = m >> 11;
                const int tt = m & (TT - 1);
                const float v0 = (acc[mt][nt][half * 2 + 0] + bb0) * scale;
                const float v1 = (acc[mt][nt][half * 2 + 1] + bb1) * scale;
                if (MODE == 0) {
                    float2 r; r.x = v0; r.y = v1;
                    *(float2*)(Y + (size_t)m * CC + nn) = r;
                } else {
                    const int h = nn >> 6;
                    const int d = nn & (HD - 1);
                    const size_t dst = (((size_t)bb * HH + h) * TT + tt) * HD + d;
                    if (which == 0) {
                        *(uint32_t*)(Yq + dst) = pkf2(v0, v1);
                    } else {
                        uint32_t hw, lw;
                        splitpack(v0, v1, hw, lw);
                        __half* dh = (which == 1) ? Ykh : Yvh;
                        __half* dl = (which == 1) ? Ykl : Yvl;
                        *(uint32_t*)(dh + dst) = hw;
                        *(uint32_t*)(dl + dst) = lw;
                    }
                }
            }
        }
    }
}

// ---------------------------------------------------------------------------
// flash5: FA2 mma.sync causal attention, 2-pass S and 2-pass PV.
// Q single fp16 (pre-scaled). K,V split hi/lo. P single-rounded fp16.
// S = Qh*Kh + Qh*Kl ; O += Ph*Vh + Ph*Vl. All f32 acc.
// CTA: 128 q-rows, 8 warps x 16 rows. KV tiles of 64 keys, 3-stage pipeline.
// ---------------------------------------------------------------------------
#define RS 144
#define QTILE_B (128*RS)                 // 18432 (single Q)
#define KVTILE_B (64*RS)                 // 9216
#define KVBUF_B (4*KVTILE_B)             // 36864 (Kh,Kl,Vh,Vl)
#define FL_SMEM (QTILE_B + 3*KVBUF_B)    // 129024

__global__ __launch_bounds__(256, 1)
void flash5(const __half* __restrict__ Q,
            const __half* __restrict__ Kh, const __half* __restrict__ Kl,
            const __half* __restrict__ Vh, const __half* __restrict__ Vl)
{
    extern __shared__ char sm[];
    const uint32_t sb = s2u(sm);
    const uint32_t kvb = sb + QTILE_B;

    const int tid = threadIdx.x;
    const int lane = tid & 31;
    const int wid = tid >> 5;
    const int qt = blockIdx.x;
    const int h  = blockIdx.y;
    const int b  = blockIdx.z;
    const size_t head = ((size_t)b * HH + h) * TT * HD;

    // ---- issue Q tile: 1024 x 16B, 4 per thread ----
#pragma unroll
    for (int i = 0; i < 4; i++) {
        const int idx = i * 256 + tid;          // 0..1023
        const int row = (idx >> 3) & 127;
        const int seg = idx & 7;
        cpa16(sb + row * RS + seg * 16,
              Q + head + (size_t)(qt * 128 + row) * HD + seg * 8);
    }
    CP_COMMIT();

    auto issue_kv = [&](int t) {
        const int kv0 = t * 64;
        const uint32_t bu = kvb + (t % 3) * KVBUF_B;
#pragma unroll
        for (int i = 0; i < 8; i++) {
            const int idx = i * 256 + tid;
            const int tile = idx >> 9;
            const int row = (idx >> 3) & 63;
            const int seg = idx & 7;
            const __half* src = (tile == 0) ? Kh : (tile == 1) ? Kl
                               : (tile == 2) ? Vh : Vl;
            cpa16(bu + tile * KVTILE_B + row * RS + seg * 16,
                  src + head + (size_t)(kv0 + row) * HD + seg * 8);
        }
        CP_COMMIT();
    };

    const int ntiles = (qt + 1) * 2;
    issue_kv(0);
    if (1 < ntiles) issue_kv(1);

    CP_WAIT(2);
    __syncthreads();

    uint32_t qf[4][4];
    {
        const uint32_t qaddr = sb + (uint32_t)((wid * 16 + (lane & 15)) * RS
                                               + (lane >> 4) * 16);
#pragma unroll
        for (int ck = 0; ck < 4; ck++)
            ldsm_x4(qf[ck], qaddr + ck * 32);
    }

    float m0 = -1e30f, m1 = -1e30f, l0 = 0.f, l1 = 0.f;
    float oacc[8][4];
#pragma unroll
    for (int nt = 0; nt < 8; nt++)
#pragma unroll
        for (int e = 0; e < 4; e++) oacc[nt][e] = 0.f;

    const int qrow = qt * 128 + wid * 16 + (lane >> 2);

    for (int t = 0; t < ntiles; t++) {
        if (t + 1 < ntiles) CP_WAIT(1);
        else                CP_WAIT(0);
        __syncthreads();
        if (t + 2 < ntiles) issue_kv(t + 2);

        const uint32_t bu = kvb + (t % 3) * KVBUF_B;

        // ---- S = Q @ (Kh + Kl)^T : 2-pass, f32 acc ----
        float sacc[8][4];
#pragma unroll
        for (int nt = 0; nt < 8; nt++)
#pragma unroll
            for (int e = 0; e < 4; e++) sacc[nt][e] = 0.f;

#pragma unroll
        for (int nt = 0; nt < 8; nt++) {
            const uint32_t ka = bu + (uint32_t)((nt * 8 + (lane & 7)) * RS
                                                + (lane >> 3) * 16);
            uint32_t khf[8], klf[8];
            ldsm_x4(khf, ka);            ldsm_x4(khf + 4, ka + 64);
            ldsm_x4(klf, ka + KVTILE_B); ldsm_x4(klf + 4, ka + KVTILE_B + 64);
#pragma unroll
            for (int ck = 0; ck < 4; ck++) {
                mma_f32(sacc[nt], qf[ck], &khf[ck * 2]);
                mma_f32(sacc[nt], qf[ck], &klf[ck * 2]);
            }
        }

        // ---- causal mask (last two tiles) ----
        if (t >= ntiles - 2) {
            const int kv0 = t * 64;
#pragma unroll
            for (int nt = 0; nt < 8; nt++)
#pragma unroll
                for (int e = 0; e < 4; e++) {
                    const int key = kv0 + nt * 8 + 2 * (lane & 3) + (e & 1);
                    const int row = qrow + ((e & 2) ? 8 : 0);
                    if (key > row) sacc[nt][e] = -1e30f;
                }
        }

        // ---- online softmax ----
#pragma unroll
        for (int hh = 0; hh < 2; hh++) {
            float& mprev = hh ? m1 : m0;
            float& lsum  = hh ? l1 : l0;
            float mx = -1e30f;
#pragma unroll
            for (int nt = 0; nt < 8; nt++)
                mx = fmaxf(mx, fmaxf(sacc[nt][hh*2], sacc[nt][hh*2+1]));
            mx = fmaxf(mx, __shfl_xor_sync(0xffffffffu, mx, 1));
            mx = fmaxf(mx, __shfl_xor_sync(0xffffffffu, mx, 2));
            const float mn = fmaxf(mprev, mx);
            const float alpha = __expf(mprev - mn);
            mprev = mn;
            float ps = 0.f;
#pragma unroll
            for (int nt = 0; nt < 8; nt++) {
                const float p0 = __expf(sacc[nt][hh*2]   - mn);
                const float p1 = __expf(sacc[nt][hh*2+1] - mn);
                ps += p0 + p1;
                sacc[nt][hh*2]   = p0;
                sacc[nt][hh*2+1] = p1;
                oacc[nt][hh*2]   *= alpha;
                oacc[nt][hh*2+1] *= alpha;
            }
            lsum = lsum * alpha + ps;
        }

        // ---- pack P single fp16 into A fragments ----
        uint32_t ap[4][4];
#pragma unroll
        for (int ck = 0; ck < 4; ck++) {
            ap[ck][0] = pkf2(sacc[2*ck][0],   sacc[2*ck][1]);
            ap[ck][1] = pkf2(sacc[2*ck][2],   sacc[2*ck][3]);
            ap[ck][2] = pkf2(sacc[2*ck+1][0], sacc[2*ck+1][1]);
            ap[ck][3] = pkf2(sacc[2*ck+1][2], sacc[2*ck+1][3]);
        }

        // ---- O += P @ (Vh + Vl) : 2-pass, f32 acc ----
#pragma unroll
        for (int nt = 0; nt < 8; nt++) {
            const uint32_t va = bu + 2 * KVTILE_B + (uint32_t)(lane * RS + nt * 16);
            uint32_t vhf[8], vlf[8];
            ldsm_x4t(vhf, va);            ldsm_x4t(vhf + 4, va + 32 * RS);
            ldsm_x4t(vlf, va + KVTILE_B); ldsm_x4t(vlf + 4, va + KVTILE_B + 32 * RS);
#pragma unroll
            for (int ck = 0; ck < 4; ck++) {
                mma_f32(oacc[nt], ap[ck], &vhf[ck * 2]);
                mma_f32(oacc[nt], ap[ck], &vlf[ck * 2]);
            }
        }
    }

    // ---- finalize: reduce l across quad, normalize, single-fp16 store ----
    l0 += __shfl_xor_sync(0xffffffffu, l0, 1);
    l0 += __shfl_xor_sync(0xffffffffu, l0, 2);
    l1 += __shfl_xor_sync(0xffffffffu, l1, 1);
    l1 += __shfl_xor_sync(0xffffffffu, l1, 2);
    const float inv0 = 1.f / l0;
    const float inv1 = 1.f / l1;

#pragma unroll
    for (int nt = 0; nt < 8; nt++) {
        const int d = nt * 8 + 2 * (lane & 3);
#pragma unroll
        for (int hh = 0; hh < 2; hh++) {
            const int row = qrow + hh * 8;
            const float inv = hh ? inv1 : inv0;
            const size_t dst = ((size_t)(b * TT + row)) * CC + h * HD + d;
            *(uint32_t*)(g_ao + dst) = pkf2(oacc[nt][hh*2] * inv,
                                            oacc[nt][hh*2+1] * inv);
        }
    }
}

// ---------------------------------------------------------------------------
extern "C" void kernel_launch(void* const* d_in, const int* in_sizes, int n_in,
                              void* d_out, int out_size)
{
    const float* x  = (const float*)d_in[0];
    const float* Wq = (const float*)d_in[1];
    const float* bq = (const float*)d_in[2];
    const float* Wk = (const float*)d_in[3];
    const float* bk = (const float*)d_in[4];
    const float* Wv = (const float*)d_in[5];
    const float* bv = (const float*)d_in[6];
    const float* Wo = (const float*)d_in[7];
    const float* bo = (const float*)d_in[8];
    float* out = (float*)d_out;

    __half *xh, *xl, *q, *kh, *kl, *vh, *vl, *ao, *wt;
    cudaGetSymbolAddress((void**)&xh, g_xh);
    cudaGetSymbolAddress((void**)&xl, g_xl);
    cudaGetSymbolAddress((void**)&q,  g_q);
    cudaGetSymbolAddress((void**)&kh, g_kh);
    cudaGetSymbolAddress((void**)&kl, g_kl);
    cudaGetSymbolAddress((void**)&vh, g_vh);
    cudaGetSymbolAddress((void**)&vl, g_vl);
    cudaGetSymbolAddress((void**)&ao, g_ao);
    cudaGetSymbolAddress((void**)&wt, g_wt);

    static bool attr_set = false;
    if (!attr_set) {
        cudaFuncSetAttribute((const void*)mmagemm<0,2>,
                             cudaFuncAttributeMaxDynamicSharedMemorySize, GEMM_SMEM);
        cudaFuncSetAttribute((const void*)mmagemm<1,3>,
                             cudaFuncAttributeMaxDynamicSharedMemorySize, GEMM_SMEM);
        cudaFuncSetAttribute((const void*)flash5,
                             cudaFuncAttributeMaxDynamicSharedMemorySize, FL_SMEM);
        attr_set = true;
    }

    const int n4 = MROWS * CC / 4;
    splitx<<<n4 / 256, 256>>>(x, xh, xl);

    dim3 wgrid(CC / 32, CC / 32, 4);
    wsplit4<<<wgrid, 256>>>(Wq, Wk, Wv, Wo, wt);

    // fused QKV projection (N = 3072), 3-pass
    dim3 qkv_grid(3 * CC / 128, MROWS / 128);   // (24, 32)
    mmagemm<1,3><<<qkv_grid, 256, GEMM_SMEM>>>(xh, xl, wt, bq, bk, bv,
                                               nullptr, q, kh, kl, vh, vl);

    dim3 att_grid(TT / 128, HH, BB);
    flash5<<<att_grid, 256, FL_SMEM>>>(q, kh, kl, vh, vl);

    // output projection (N = 1024), 2-pass (A = ao single fp16)
    dim3 out_grid(CC / 128, MROWS / 128);       // (8, 32)
    mmagemm<0,2><<<out_grid, 256, GEMM_SMEM>>>(ao, nullptr, wt + 6*(size_t)CC*CC,
                                               bo, nullptr, nullptr,
                                               out, nullptr, nullptr, nullptr,
                                               nullptr, nullptr);
}

// round 12
// speedup vs baseline: 1.6023x; 1.1864x over previous
#include <cuda_runtime.h>
#include <cuda_fp16.h>
#include <stdint.h>
#include <math.h>

// Problem constants
#define BB 2
#define TT 2048
#define CC 1024
#define HH 16
#define HD 64
#define MROWS (BB*TT)

// ---------------------------------------------------------------------------
// Scratch (allocation-free rule: __device__ globals)
// ---------------------------------------------------------------------------
__device__ __half g_x  [MROWS*CC];     // x single fp16
__device__ __half g_q  [MROWS*CC];     // Q single fp16, pre-scaled, [B,H,T,HD]
__device__ __half g_kh [MROWS*CC];
__device__ __half g_kl [MROWS*CC];
__device__ __half g_vh [MROWS*CC];
__device__ __half g_vl [MROWS*CC];
__device__ __half g_ao [MROWS*CC];     // attention out single fp16, [B*T, C]
__device__ __half g_wt [8*CC*CC];      // [w*2+{hi,lo}][n][k]  (W^T, K-major)

// ---------------------------------------------------------------------------
// Warp-MMA helpers (base sm_80+ features)
// ---------------------------------------------------------------------------
__device__ __forceinline__ uint32_t s2u(const void* p) {
    uint32_t a;
    asm("{ .reg .u64 t; cvta.to.shared.u64 t, %1; cvt.u32.u64 %0, t; }"
        : "=r"(a) : "l"(p));
    return a;
}
__device__ __forceinline__ void ldsm_x4(uint32_t* r, uint32_t addr) {
    asm volatile("ldmatrix.sync.aligned.m8n8.x4.shared.b16 {%0,%1,%2,%3}, [%4];"
        : "=r"(r[0]), "=r"(r[1]), "=r"(r[2]), "=r"(r[3]) : "r"(addr));
}
__device__ __forceinline__ void ldsm_x4t(uint32_t* r, uint32_t addr) {
    asm volatile("ldmatrix.sync.aligned.m8n8.x4.trans.shared.b16 {%0,%1,%2,%3}, [%4];"
        : "=r"(r[0]), "=r"(r[1]), "=r"(r[2]), "=r"(r[3]) : "r"(addr));
}
__device__ __forceinline__ void mma_f32(float* c, const uint32_t* a, const uint32_t* b) {
    asm volatile(
        "mma.sync.aligned.m16n8k16.row.col.f32.f16.f16.f32 "
        "{%0,%1,%2,%3}, {%4,%5,%6,%7}, {%8,%9}, {%0,%1,%2,%3};"
        : "+f"(c[0]), "+f"(c[1]), "+f"(c[2]), "+f"(c[3])
        : "r"(a[0]), "r"(a[1]), "r"(a[2]), "r"(a[3]), "r"(b[0]), "r"(b[1]));
}
__device__ __forceinline__ void cpa16(uint32_t dst, const void* src) {
    asm volatile("cp.async.ca.shared.global [%0], [%1], 16;" :: "r"(dst), "l"(src));
}
#define CP_COMMIT() asm volatile("cp.async.commit_group;" ::: "memory")
#define CP_WAIT(n)  asm volatile("cp.async.wait_group %0;" :: "n"(n) : "memory")

__device__ __forceinline__ void split1(float v, __half& h, __half& l) {
    h = __float2half_rn(v);
    l = __float2half_rn(v - __half2float(h));
}
__device__ __forceinline__ uint32_t pk2(__half a, __half b) {
    __half2 t = __halves2half2(a, b);
    return *(uint32_t*)&t;
}
__device__ __forceinline__ uint32_t pkf2(float a, float b) {
    __half2 t = __floats2half2_rn(a, b);
    return *(uint32_t*)&t;
}
__device__ __forceinline__ void splitpack(float a, float b, uint32_t& hi, uint32_t& lo) {
    __half ah, al, bh, bl;
    split1(a, ah, al); split1(b, bh, bl);
    hi = pk2(ah, bh); lo = pk2(al, bl);
}

// ---------------------------------------------------------------------------
// Prep kernels
// ---------------------------------------------------------------------------
// x -> single fp16 (2-pass QKV: no lo component needed)
__global__ void castx(const float* __restrict__ x, __half* __restrict__ hi)
{
    const int i = blockIdx.x * blockDim.x + threadIdx.x;
    float4 v = ((const float4*)x)[i];
    uint2 hw = { pkf2(v.x, v.y), pkf2(v.z, v.w) };
    ((uint2*)hi)[i] = hw;
}

__global__ __launch_bounds__(256)
void wsplit4(const float* __restrict__ W0, const float* __restrict__ W1,
             const float* __restrict__ W2, const float* __restrict__ W3,
             __half* __restrict__ wt)
{
    __shared__ float t[32][33];
    const int wsel = blockIdx.z;
    const float* W = (wsel == 0) ? W0 : (wsel == 1) ? W1 : (wsel == 2) ? W2 : W3;
    __half* th = wt + (size_t)(2 * wsel)     * CC * CC;
    __half* tl = wt + (size_t)(2 * wsel + 1) * CC * CC;

    const int n0 = blockIdx.x * 32;
    const int k0 = blockIdx.y * 32;
    const int tx = threadIdx.x & 31;
    const int ty = threadIdx.x >> 5;
#pragma unroll
    for (int r = 0; r < 4; r++) {
        const int row = ty + r * 8;
        t[row][tx] = W[(size_t)(k0 + row) * CC + n0 + tx];
    }
    __syncthreads();
#pragma unroll
    for (int r = 0; r < 4; r++) {
        const int row = ty + r * 8;
        const float v = t[tx][row];
        __half h, l;
        split1(v, h, l);
        th[(size_t)(n0 + row) * CC + k0 + tx] = h;
        tl[(size_t)(n0 + row) * CC + k0 + tx] = l;
    }
}

// ---------------------------------------------------------------------------
// mma.sync fp16 GEMM (128x128 CTA tile, 4 stages, f32-acc), 2-pass:
// Y = A*(Bh+Bl) + bias, A single fp16.
// MODE 1 (fused QKV): N=3072; Q -> single fp16 scaled; K,V -> split hi/lo.
// MODE 0 (out proj):  N=1024; fp32 out.
// ---------------------------------------------------------------------------
#define KC 16
#define TSTRIDE 48
#define TILE_B (128*TSTRIDE)
#define BUF_B  (4*TILE_B)            // 24576 (A slot, unused Al slot, Bh, Bl)
#define GEMM_SMEM (4*BUF_B)          // 98304

template<int MODE>
__global__ __launch_bounds__(256, 2)
void mmagemm(const __half* __restrict__ Ah,
             const __half* __restrict__ Wt,
             const float* __restrict__ b0, const float* __restrict__ b1,
             const float* __restrict__ b2,
             float* __restrict__ Y,
             __half* __restrict__ Yq,
             __half* __restrict__ Ykh, __half* __restrict__ Ykl,
             __half* __restrict__ Yvh, __half* __restrict__ Yvl)
{
    extern __shared__ char dsm[];
    const uint32_t sb = s2u(dsm);

    const int tid = threadIdx.x;
    const int lane = tid & 31;
    const int wid = tid >> 5;
    const int warp_m = wid & 1;
    const int warp_n = wid >> 1;
    const int bm = blockIdx.y * 128;
    const int bn = blockIdx.x * 128;

    const int which = (MODE == 1) ? (bn >> 10) : 0;
    const int nw = bn & (CC - 1);
    const __half* Bh = Wt + (size_t)(2 * which)     * CC * CC;
    const __half* Bl = Wt + (size_t)(2 * which + 1) * CC * CC;
    const float* bias = (MODE == 0) ? b0 : (which == 0) ? b0 : (which == 1) ? b1 : b2;
    const float scale = (MODE == 1 && which == 0) ? 0.125f : 1.0f;

    float acc[4][4][4];
#pragma unroll
    for (int i = 0; i < 4; i++)
#pragma unroll
        for (int j = 0; j < 4; j++)
#pragma unroll
            for (int q = 0; q < 4; q++) acc[i][j][q] = 0.f;

    auto issue = [&](int c) {
        const int k0 = c * KC;
        const uint32_t bu = sb + (c & 3) * BUF_B;
#pragma unroll
        for (int i = 0; i < 4; i++) {
            if (i == 1) continue;                 // no A-lo tile (2-pass)
            const int j = i * 256 + tid;
            const int row = (j >> 1) & 127;
            const int seg = j & 1;
            const __half* s = (i == 0) ? Ah : (i == 2) ? Bh : Bl;
            const int rb = (i < 2) ? bm : nw;
            cpa16(bu + i * TILE_B + row * TSTRIDE + seg * 16,
                  s + (size_t)(rb + row) * CC + k0 + seg * 8);
        }
        CP_COMMIT();
    };

    issue(0); issue(1); issue(2);

    const uint32_t a_off = (uint32_t)((warp_m * 64 + (lane & 15)) * TSTRIDE
                                      + (lane >> 4) * 16);
    const uint32_t b_off = (uint32_t)((warp_n * 32 + ((lane >> 4) * 8) + (lane & 7)) * TSTRIDE
                                      + ((lane >> 3) & 1) * 16);

    for (int c = 0; c < 64; c++) {
        CP_WAIT(2);
        __syncthreads();
        if (c + 3 < 64) issue(c + 3);

        const uint32_t bu = sb + (c & 3) * BUF_B;
        uint32_t af[4][4];
        uint32_t bhf[2][4], blf[2][4];

#pragma unroll
        for (int p = 0; p < 2; p++) {
            ldsm_x4(bhf[p], bu + 2*TILE_B + b_off + (uint32_t)(p * 16 * TSTRIDE));
            ldsm_x4(blf[p], bu + 3*TILE_B + b_off + (uint32_t)(p * 16 * TSTRIDE));
        }
#pragma unroll
        for (int mt = 0; mt < 4; mt++)
            ldsm_x4(af[mt], bu + a_off + (uint32_t)(mt * 16 * TSTRIDE));
        // pass 1: A*Bh
#pragma unroll
        for (int mt = 0; mt < 4; mt++)
#pragma unroll
            for (int nt = 0; nt < 4; nt++)
                mma_f32(acc[mt][nt], af[mt], &bhf[nt >> 1][(nt & 1) * 2]);
        // pass 2: A*Bl
#pragma unroll
        for (int mt = 0; mt < 4; mt++)
#pragma unroll
            for (int nt = 0; nt < 4; nt++)
                mma_f32(acc[mt][nt], af[mt], &blf[nt >> 1][(nt & 1) * 2]);
    }

#pragma unroll
    for (int mt = 0; mt < 4; mt++) {
#pragma unroll
        for (int nt = 0; nt < 4; nt++) {
            const int m0 = bm + warp_m * 64 + mt * 16 + (lane >> 2);
            const int nn = nw + warp_n * 32 + nt * 8 + 2 * (lane & 3);
            const float bb0 = __ldg(bias + nn);
            const float bb1 = __ldg(bias + nn + 1);
#pragma unroll
            for (int half = 0; half < 2; half++) {
                const int m = m0 + half * 8;
                const int bb = m >> 11;
                const int tt = m & (TT - 1);
                const float v0 = (acc[mt][nt][half * 2 + 0] + bb0) * scale;
                const float v1 = (acc[mt][nt][half * 2 + 1] + bb1) * scale;
                if (MODE == 0) {
                    float2 r; r.x = v0; r.y = v1;
                    *(float2*)(Y + (size_t)m * CC + nn) = r;
                } else {
                    const int h = nn >> 6;
                    const int d = nn & (HD - 1);
                    const size_t dst = (((size_t)bb * HH + h) * TT + tt) * HD + d;
                    if (which == 0) {
                        *(uint32_t*)(Yq + dst) = pkf2(v0, v1);
                    } else {
                        uint32_t hw, lw;
                        splitpack(v0, v1, hw, lw);
                        __half* dh = (which == 1) ? Ykh : Yvh;
                        __half* dl = (which == 1) ? Ykl : Yvl;
                        *(uint32_t*)(dh + dst) = hw;
                        *(uint32_t*)(dl + dst) = lw;
                    }
                }
            }
        }
    }
}

// ---------------------------------------------------------------------------
// flash5: FA2 mma.sync causal attention, 2-pass S and 2-pass PV.
// Q single fp16 (pre-scaled). K,V split hi/lo. P single-rounded fp16.
// (unchanged from round 11)
// ---------------------------------------------------------------------------
#define RS 144
#define QTILE_B (128*RS)                 // 18432 (single Q)
#define KVTILE_B (64*RS)                 // 9216
#define KVBUF_B (4*KVTILE_B)             // 36864 (Kh,Kl,Vh,Vl)
#define FL_SMEM (QTILE_B + 3*KVBUF_B)    // 129024

__global__ __launch_bounds__(256, 1)
void flash5(const __half* __restrict__ Q,
            const __half* __restrict__ Kh, const __half* __restrict__ Kl,
            const __half* __restrict__ Vh, const __half* __restrict__ Vl)
{
    extern __shared__ char sm[];
    const uint32_t sb = s2u(sm);
    const uint32_t kvb = sb + QTILE_B;

    const int tid = threadIdx.x;
    const int lane = tid & 31;
    const int wid = tid >> 5;
    const int qt = blockIdx.x;
    const int h  = blockIdx.y;
    const int b  = blockIdx.z;
    const size_t head = ((size_t)b * HH + h) * TT * HD;

#pragma unroll
    for (int i = 0; i < 4; i++) {
        const int idx = i * 256 + tid;
        const int row = (idx >> 3) & 127;
        const int seg = idx & 7;
        cpa16(sb + row * RS + seg * 16,
              Q + head + (size_t)(qt * 128 + row) * HD + seg * 8);
    }
    CP_COMMIT();

    auto issue_kv = [&](int t) {
        const int kv0 = t * 64;
        const uint32_t bu = kvb + (t % 3) * KVBUF_B;
#pragma unroll
        for (int i = 0; i < 8; i++) {
            const int idx = i * 256 + tid;
            const int tile = idx >> 9;
            const int row = (idx >> 3) & 63;
            const int seg = idx & 7;
            const __half* src = (tile == 0) ? Kh : (tile == 1) ? Kl
                               : (tile == 2) ? Vh : Vl;
            cpa16(bu + tile * KVTILE_B + row * RS + seg * 16,
                  src + head + (size_t)(kv0 + row) * HD + seg * 8);
        }
        CP_COMMIT();
    };

    const int ntiles = (qt + 1) * 2;
    issue_kv(0);
    if (1 < ntiles) issue_kv(1);

    CP_WAIT(2);
    __syncthreads();

    uint32_t qf[4][4];
    {
        const uint32_t qaddr = sb + (uint32_t)((wid * 16 + (lane & 15)) * RS
                                               + (lane >> 4) * 16);
#pragma unroll
        for (int ck = 0; ck < 4; ck++)
            ldsm_x4(qf[ck], qaddr + ck * 32);
    }

    float m0 = -1e30f, m1 = -1e30f, l0 = 0.f, l1 = 0.f;
    float oacc[8][4];
#pragma unroll
    for (int nt = 0; nt < 8; nt++)
#pragma unroll
        for (int e = 0; e < 4; e++) oacc[nt][e] = 0.f;

    const int qrow = qt * 128 + wid * 16 + (lane >> 2);

    for (int t = 0; t < ntiles; t++) {
        if (t + 1 < ntiles) CP_WAIT(1);
        else                CP_WAIT(0);
        __syncthreads();
        if (t + 2 < ntiles) issue_kv(t + 2);

        const uint32_t bu = kvb + (t % 3) * KVBUF_B;

        // ---- S = Q @ (Kh + Kl)^T : 2-pass, f32 acc ----
        float sacc[8][4];
#pragma unroll
        for (int nt = 0; nt < 8; nt++)
#pragma unroll
            for (int e = 0; e < 4; e++) sacc[nt][e] = 0.f;

#pragma unroll
        for (int nt = 0; nt < 8; nt++) {
            const uint32_t ka = bu + (uint32_t)((nt * 8 + (lane & 7)) * RS
                                                + (lane >> 3) * 16);
            uint32_t khf[8], klf[8];
            ldsm_x4(khf, ka);            ldsm_x4(khf + 4, ka + 64);
            ldsm_x4(klf, ka + KVTILE_B); ldsm_x4(klf + 4, ka + KVTILE_B + 64);
#pragma unroll
            for (int ck = 0; ck < 4; ck++) {
                mma_f32(sacc[nt], qf[ck], &khf[ck * 2]);
                mma_f32(sacc[nt], qf[ck], &klf[ck * 2]);
            }
        }

        // ---- causal mask (last two tiles) ----
        if (t >= ntiles - 2) {
            const int kv0 = t * 64;
#pragma unroll
            for (int nt = 0; nt < 8; nt++)
#pragma unroll
                for (int e = 0; e < 4; e++) {
                    const int key = kv0 + nt * 8 + 2 * (lane & 3) + (e & 1);
                    const int row = qrow + ((e & 2) ? 8 : 0);
                    if (key > row) sacc[nt][e] = -1e30f;
                }
        }

        // ---- online softmax ----
#pragma unroll
        for (int hh = 0; hh < 2; hh++) {
            float& mprev = hh ? m1 : m0;
            float& lsum  = hh ? l1 : l0;
            float mx = -1e30f;
#pragma unroll
            for (int nt = 0; nt < 8; nt++)
                mx = fmaxf(mx, fmaxf(sacc[nt][hh*2], sacc[nt][hh*2+1]));
            mx = fmaxf(mx, __shfl_xor_sync(0xffffffffu, mx, 1));
            mx = fmaxf(mx, __shfl_xor_sync(0xffffffffu, mx, 2));
            const float mn = fmaxf(mprev, mx);
            const float alpha = __expf(mprev - mn);
            mprev = mn;
            float ps = 0.f;
#pragma unroll
            for (int nt = 0; nt < 8; nt++) {
                const float p0 = __expf(sacc[nt][hh*2]   - mn);
                const float p1 = __expf(sacc[nt][hh*2+1] - mn);
                ps += p0 + p1;
                sacc[nt][hh*2]   = p0;
                sacc[nt][hh*2+1] = p1;
                oacc[nt][hh*2]   *= alpha;
                oacc[nt][hh*2+1] *= alpha;
            }
            lsum = lsum * alpha + ps;
        }

        // ---- pack P single fp16 into A fragments ----
        uint32_t ap[4][4];
#pragma unroll
        for (int ck = 0; ck < 4; ck++) {
            ap[ck][0] = pkf2(sacc[2*ck][0],   sacc[2*ck][1]);
            ap[ck][1] = pkf2(sacc[2*ck][2],   sacc[2*ck][3]);
            ap[ck][2] = pkf2(sacc[2*ck+1][0], sacc[2*ck+1][1]);
            ap[ck][3] = pkf2(sacc[2*ck+1][2], sacc[2*ck+1][3]);
        }

        // ---- O += P @ (Vh + Vl) : 2-pass, f32 acc ----
#pragma unroll
        for (int nt = 0; nt < 8; nt++) {
            const uint32_t va = bu + 2 * KVTILE_B + (uint32_t)(lane * RS + nt * 16);
            uint32_t vhf[8], vlf[8];
            ldsm_x4t(vhf, va);            ldsm_x4t(vhf + 4, va + 32 * RS);
            ldsm_x4t(vlf, va + KVTILE_B); ldsm_x4t(vlf + 4, va + KVTILE_B + 32 * RS);
#pragma unroll
            for (int ck = 0; ck < 4; ck++) {
                mma_f32(oacc[nt], ap[ck], &vhf[ck * 2]);
                mma_f32(oacc[nt], ap[ck], &vlf[ck * 2]);
            }
        }
    }

    // ---- finalize ----
    l0 += __shfl_xor_sync(0xffffffffu, l0, 1);
    l0 += __shfl_xor_sync(0xffffffffu, l0, 2);
    l1 += __shfl_xor_sync(0xffffffffu, l1, 1);
    l1 += __shfl_xor_sync(0xffffffffu, l1, 2);
    const float inv0 = 1.f / l0;
    const float inv1 = 1.f / l1;

#pragma unroll
    for (int nt = 0; nt < 8; nt++) {
        const int d = nt * 8 + 2 * (lane & 3);
#pragma unroll
        for (int hh = 0; hh < 2; hh++) {
            const int row = qrow + hh * 8;
            const float inv = hh ? inv1 : inv0;
            const size_t dst = ((size_t)(b * TT + row)) * CC + h * HD + d;
            *(uint32_t*)(g_ao + dst) = pkf2(oacc[nt][hh*2] * inv,
                                            oacc[nt][hh*2+1] * inv);
        }
    }
}

// ---------------------------------------------------------------------------
extern "C" void kernel_launch(void* const* d_in, const int* in_sizes, int n_in,
                              void* d_out, int out_size)
{
    const float* x  = (const float*)d_in[0];
    const float* Wq = (const float*)d_in[1];
    const float* bq = (const float*)d_in[2];
    const float* Wk = (const float*)d_in[3];
    const float* bk = (const float*)d_in[4];
    const float* Wv = (const float*)d_in[5];
    const float* bv = (const float*)d_in[6];
    const float* Wo = (const float*)d_in[7];
    const float* bo = (const float*)d_in[8];
    float* out = (float*)d_out;

    __half *xs, *q, *kh, *kl, *vh, *vl, *ao, *wt;
    cudaGetSymbolAddress((void**)&xs, g_x);
    cudaGetSymbolAddress((void**)&q,  g_q);
    cudaGetSymbolAddress((void**)&kh, g_kh);
    cudaGetSymbolAddress((void**)&kl, g_kl);
    cudaGetSymbolAddress((void**)&vh, g_vh);
    cudaGetSymbolAddress((void**)&vl, g_vl);
    cudaGetSymbolAddress((void**)&ao, g_ao);
    cudaGetSymbolAddress((void**)&wt, g_wt);

    static bool attr_set = false;
    if (!attr_set) {
        cudaFuncSetAttribute((const void*)mmagemm<0>,
                             cudaFuncAttributeMaxDynamicSharedMemorySize, GEMM_SMEM);
        cudaFuncSetAttribute((const void*)mmagemm<1>,
                             cudaFuncAttributeMaxDynamicSharedMemorySize, GEMM_SMEM);
        cudaFuncSetAttribute((const void*)flash5,
                             cudaFuncAttributeMaxDynamicSharedMemorySize, FL_SMEM);
        attr_set = true;
    }

    const int n4 = MROWS * CC / 4;
    castx<<<n4 / 256, 256>>>(x, xs);

    dim3 wgrid(CC / 32, CC / 32, 4);
    wsplit4<<<wgrid, 256>>>(Wq, Wk, Wv, Wo, wt);

    // fused QKV projection (N = 3072), 2-pass
    dim3 qkv_grid(3 * CC / 128, MROWS / 128);   // (24, 32)
    mmagemm<1><<<qkv_grid, 256, GEMM_SMEM>>>(xs, wt, bq, bk, bv,
                                             nullptr, q, kh, kl, vh, vl);

    dim3 att_grid(TT / 128, HH, BB);
    flash5<<<att_grid, 256, FL_SMEM>>>(q, kh, kl, vh, vl);

    // output projection (N = 1024), 2-pass (A = ao single fp16)
    dim3 out_grid(CC / 128, MROWS / 128);       // (8, 32)
    mmagemm<0><<<out_grid, 256, GEMM_SMEM>>>(ao, wt + 6*(size_t)CC*CC,
                                             bo, nullptr, nullptr,
                                             out, nullptr, nullptr, nullptr,
                                             nullptr, nullptr);
}

// round 13
// speedup vs baseline: 1.8456x; 1.1518x over previous
#include <cuda_runtime.h>
#include <cuda_fp16.h>
#include <stdint.h>
#include <math.h>

// Problem constants
#define BB 2
#define TT 2048
#define CC 1024
#define HH 16
#define HD 64
#define MROWS (BB*TT)

// ---------------------------------------------------------------------------
// Scratch (allocation-free rule: __device__ globals)
// ---------------------------------------------------------------------------
__device__ __half g_x  [MROWS*CC];     // x single fp16
__device__ __half g_q  [MROWS*CC];     // Q single fp16, pre-scaled, [B,H,T,HD]
__device__ __half g_k  [MROWS*CC];     // K single fp16, [B,H,T,HD]
__device__ __half g_v  [MROWS*CC];     // V single fp16, [B,H,T,HD]
__device__ __half g_ao [MROWS*CC];     // attention out single fp16, [B*T, C]
__device__ __half g_wt [8*CC*CC];      // [w*2+{hi,lo}][n][k]  (W^T, K-major)

// ---------------------------------------------------------------------------
// Warp-MMA helpers (base sm_80+ features)
// ---------------------------------------------------------------------------
__device__ __forceinline__ uint32_t s2u(const void* p) {
    uint32_t a;
    asm("{ .reg .u64 t; cvta.to.shared.u64 t, %1; cvt.u32.u64 %0, t; }"
        : "=r"(a) : "l"(p));
    return a;
}
__device__ __forceinline__ void ldsm_x4(uint32_t* r, uint32_t addr) {
    asm volatile("ldmatrix.sync.aligned.m8n8.x4.shared.b16 {%0,%1,%2,%3}, [%4];"
        : "=r"(r[0]), "=r"(r[1]), "=r"(r[2]), "=r"(r[3]) : "r"(addr));
}
__device__ __forceinline__ void ldsm_x4t(uint32_t* r, uint32_t addr) {
    asm volatile("ldmatrix.sync.aligned.m8n8.x4.trans.shared.b16 {%0,%1,%2,%3}, [%4];"
        : "=r"(r[0]), "=r"(r[1]), "=r"(r[2]), "=r"(r[3]) : "r"(addr));
}
__device__ __forceinline__ void mma_f32(float* c, const uint32_t* a, const uint32_t* b) {
    asm volatile(
        "mma.sync.aligned.m16n8k16.row.col.f32.f16.f16.f32 "
        "{%0,%1,%2,%3}, {%4,%5,%6,%7}, {%8,%9}, {%0,%1,%2,%3};"
        : "+f"(c[0]), "+f"(c[1]), "+f"(c[2]), "+f"(c[3])
        : "r"(a[0]), "r"(a[1]), "r"(a[2]), "r"(a[3]), "r"(b[0]), "r"(b[1]));
}
__device__ __forceinline__ void cpa16(uint32_t dst, const void* src) {
    asm volatile("cp.async.ca.shared.global [%0], [%1], 16;" :: "r"(dst), "l"(src));
}
#define CP_COMMIT() asm volatile("cp.async.commit_group;" ::: "memory")
#define CP_WAIT(n)  asm volatile("cp.async.wait_group %0;" :: "n"(n) : "memory")

__device__ __forceinline__ void split1(float v, __half& h, __half& l) {
    h = __float2half_rn(v);
    l = __float2half_rn(v - __half2float(h));
}
__device__ __forceinline__ uint32_t pkf2(float a, float b) {
    __half2 t = __floats2half2_rn(a, b);
    return *(uint32_t*)&t;
}

// ---------------------------------------------------------------------------
// Prep kernels
// ---------------------------------------------------------------------------
__global__ void castx(const float* __restrict__ x, __half* __restrict__ hi)
{
    const int i = blockIdx.x * blockDim.x + threadIdx.x;
    float4 v = ((const float4*)x)[i];
    uint2 hw = { pkf2(v.x, v.y), pkf2(v.z, v.w) };
    ((uint2*)hi)[i] = hw;
}

__global__ __launch_bounds__(256)
void wsplit4(const float* __restrict__ W0, const float* __restrict__ W1,
             const float* __restrict__ W2, const float* __restrict__ W3,
             __half* __restrict__ wt)
{
    __shared__ float t[32][33];
    const int wsel = blockIdx.z;
    const float* W = (wsel == 0) ? W0 : (wsel == 1) ? W1 : (wsel == 2) ? W2 : W3;
    __half* th = wt + (size_t)(2 * wsel)     * CC * CC;
    __half* tl = wt + (size_t)(2 * wsel + 1) * CC * CC;

    const int n0 = blockIdx.x * 32;
    const int k0 = blockIdx.y * 32;
    const int tx = threadIdx.x & 31;
    const int ty = threadIdx.x >> 5;
#pragma unroll
    for (int r = 0; r < 4; r++) {
        const int row = ty + r * 8;
        t[row][tx] = W[(size_t)(k0 + row) * CC + n0 + tx];
    }
    __syncthreads();
#pragma unroll
    for (int r = 0; r < 4; r++) {
        const int row = ty + r * 8;
        const float v = t[tx][row];
        __half h, l;
        split1(v, h, l);
        th[(size_t)(n0 + row) * CC + k0 + tx] = h;
        tl[(size_t)(n0 + row) * CC + k0 + tx] = l;
    }
}

// ---------------------------------------------------------------------------
// mma.sync fp16 GEMM (128x128 CTA tile, 4 stages, f32-acc), 2-pass:
// Y = A*(Bh+Bl) + bias, A single fp16.
// MODE 1 (fused QKV): N=3072; q/k/v all single fp16 out, permuted; q scaled.
// MODE 0 (out proj):  N=1024; fp32 out.
// ---------------------------------------------------------------------------
#define KC 16
#define TSTRIDE 48
#define TILE_B (128*TSTRIDE)
#define BUF_B  (4*TILE_B)            // 24576 (A slot, unused slot, Bh, Bl)
#define GEMM_SMEM (4*BUF_B)          // 98304

template<int MODE>
__global__ __launch_bounds__(256, 2)
void mmagemm(const __half* __restrict__ Ah,
             const __half* __restrict__ Wt,
             const float* __restrict__ b0, const float* __restrict__ b1,
             const float* __restrict__ b2,
             float* __restrict__ Y,
             __half* __restrict__ Yq, __half* __restrict__ Yk,
             __half* __restrict__ Yv)
{
    extern __shared__ char dsm[];
    const uint32_t sb = s2u(dsm);

    const int tid = threadIdx.x;
    const int lane = tid & 31;
    const int wid = tid >> 5;
    const int warp_m = wid & 1;
    const int warp_n = wid >> 1;
    const int bm = blockIdx.y * 128;
    const int bn = blockIdx.x * 128;

    const int which = (MODE == 1) ? (bn >> 10) : 0;
    const int nw = bn & (CC - 1);
    const __half* Bh = Wt + (size_t)(2 * which)     * CC * CC;
    const __half* Bl = Wt + (size_t)(2 * which + 1) * CC * CC;
    const float* bias = (MODE == 0) ? b0 : (which == 0) ? b0 : (which == 1) ? b1 : b2;
    const float scale = (MODE == 1 && which == 0) ? 0.125f : 1.0f;

    float acc[4][4][4];
#pragma unroll
    for (int i = 0; i < 4; i++)
#pragma unroll
        for (int j = 0; j < 4; j++)
#pragma unroll
            for (int q = 0; q < 4; q++) acc[i][j][q] = 0.f;

    auto issue = [&](int c) {
        const int k0 = c * KC;
        const uint32_t bu = sb + (c & 3) * BUF_B;
#pragma unroll
        for (int i = 0; i < 4; i++) {
            if (i == 1) continue;                 // unused slot (2-pass)
            const int j = i * 256 + tid;
            const int row = (j >> 1) & 127;
            const int seg = j & 1;
            const __half* s = (i == 0) ? Ah : (i == 2) ? Bh : Bl;
            const int rb = (i < 2) ? bm : nw;
            cpa16(bu + i * TILE_B + row * TSTRIDE + seg * 16,
                  s + (size_t)(rb + row) * CC + k0 + seg * 8);
        }
        CP_COMMIT();
    };

    issue(0); issue(1); issue(2);

    const uint32_t a_off = (uint32_t)((warp_m * 64 + (lane & 15)) * TSTRIDE
                                      + (lane >> 4) * 16);
    const uint32_t b_off = (uint32_t)((warp_n * 32 + ((lane >> 4) * 8) + (lane & 7)) * TSTRIDE
                                      + ((lane >> 3) & 1) * 16);

    for (int c = 0; c < 64; c++) {
        CP_WAIT(2);
        __syncthreads();
        if (c + 3 < 64) issue(c + 3);

        const uint32_t bu = sb + (c & 3) * BUF_B;
        uint32_t af[4][4];
        uint32_t bhf[2][4], blf[2][4];

#pragma unroll
        for (int p = 0; p < 2; p++) {
            ldsm_x4(bhf[p], bu + 2*TILE_B + b_off + (uint32_t)(p * 16 * TSTRIDE));
            ldsm_x4(blf[p], bu + 3*TILE_B + b_off + (uint32_t)(p * 16 * TSTRIDE));
        }
#pragma unroll
        for (int mt = 0; mt < 4; mt++)
            ldsm_x4(af[mt], bu + a_off + (uint32_t)(mt * 16 * TSTRIDE));
        // pass 1: A*Bh
#pragma unroll
        for (int mt = 0; mt < 4; mt++)
#pragma unroll
            for (int nt = 0; nt < 4; nt++)
                mma_f32(acc[mt][nt], af[mt], &bhf[nt >> 1][(nt & 1) * 2]);
        // pass 2: A*Bl
#pragma unroll
        for (int mt = 0; mt < 4; mt++)
#pragma unroll
            for (int nt = 0; nt < 4; nt++)
                mma_f32(acc[mt][nt], af[mt], &blf[nt >> 1][(nt & 1) * 2]);
    }

#pragma unroll
    for (int mt = 0; mt < 4; mt++) {
#pragma unroll
        for (int nt = 0; nt < 4; nt++) {
            const int m0 = bm + warp_m * 64 + mt * 16 + (lane >> 2);
            const int nn = nw + warp_n * 32 + nt * 8 + 2 * (lane & 3);
            const float bb0 = __ldg(bias + nn);
            const float bb1 = __ldg(bias + nn + 1);
#pragma unroll
            for (int half = 0; half < 2; half++) {
                const int m = m0 + half * 8;
                const int bb = m >> 11;
                const int tt = m & (TT - 1);
                const float v0 = (acc[mt][nt][half * 2 + 0] + bb0) * scale;
                const float v1 = (acc[mt][nt][half * 2 + 1] + bb1) * scale;
                if (MODE == 0) {
                    float2 r; r.x = v0; r.y = v1;
                    *(float2*)(Y + (size_t)m * CC + nn) = r;
                } else {
                    const int h = nn >> 6;
                    const int d = nn & (HD - 1);
                    const size_t dst = (((size_t)bb * HH + h) * TT + tt) * HD + d;
                    __half* dp = (which == 0) ? Yq : (which == 1) ? Yk : Yv;
                    *(uint32_t*)(dp + dst) = pkf2(v0, v1);
                }
            }
        }
    }
}

// ---------------------------------------------------------------------------
// flash6: FA2 mma.sync causal attention, single-pass S and single-pass PV.
// Q, K, V all single fp16 (Q pre-scaled). P single-rounded fp16. f32 acc.
// CTA: 128 q-rows, 8 warps x 16 rows. KV tiles of 64 keys, 3-stage pipeline.
// ---------------------------------------------------------------------------
#define RS 144
#define QTILE_B (128*RS)                 // 18432 (single Q)
#define KVTILE_B (64*RS)                 // 9216
#define KVBUF_B (2*KVTILE_B)             // 18432 (K, V)
#define FL_SMEM (QTILE_B + 3*KVBUF_B)    // 73728

__global__ __launch_bounds__(256, 1)
void flash6(const __half* __restrict__ K_, const __half* __restrict__ Q,
            const __half* __restrict__ V_)
{
    extern __shared__ char sm[];
    const uint32_t sb = s2u(sm);
    const uint32_t kvb = sb + QTILE_B;

    const int tid = threadIdx.x;
    const int lane = tid & 31;
    const int wid = tid >> 5;
    const int qt = blockIdx.x;
    const int h  = blockIdx.y;
    const int b  = blockIdx.z;
    const size_t head = ((size_t)b * HH + h) * TT * HD;

    // ---- issue Q tile: 1024 x 16B, 4 per thread ----
#pragma unroll
    for (int i = 0; i < 4; i++) {
        const int idx = i * 256 + tid;
        const int row = (idx >> 3) & 127;
        const int seg = idx & 7;
        cpa16(sb + row * RS + seg * 16,
              Q + head + (size_t)(qt * 128 + row) * HD + seg * 8);
    }
    CP_COMMIT();

    auto issue_kv = [&](int t) {
        const int kv0 = t * 64;
        const uint32_t bu = kvb + (t % 3) * KVBUF_B;
#pragma unroll
        for (int i = 0; i < 4; i++) {
            const int idx = i * 256 + tid;       // 0..1023
            const int tile = idx >> 9;           // 0..1 (K, V)
            const int row = (idx >> 3) & 63;
            const int seg = idx & 7;
            const __half* src = (tile == 0) ? K_ : V_;
            cpa16(bu + tile * KVTILE_B + row * RS + seg * 16,
                  src + head + (size_t)(kv0 + row) * HD + seg * 8);
        }
        CP_COMMIT();
    };

    const int ntiles = (qt + 1) * 2;
    issue_kv(0);
    if (1 < ntiles) issue_kv(1);

    CP_WAIT(2);
    __syncthreads();

    uint32_t qf[4][4];
    {
        const uint32_t qaddr = sb + (uint32_t)((wid * 16 + (lane & 15)) * RS
                                               + (lane >> 4) * 16);
#pragma unroll
        for (int ck = 0; ck < 4; ck++)
            ldsm_x4(qf[ck], qaddr + ck * 32);
    }

    float m0 = -1e30f, m1 = -1e30f, l0 = 0.f, l1 = 0.f;
    float oacc[8][4];
#pragma unroll
    for (int nt = 0; nt < 8; nt++)
#pragma unroll
        for (int e = 0; e < 4; e++) oacc[nt][e] = 0.f;

    const int qrow = qt * 128 + wid * 16 + (lane >> 2);

    for (int t = 0; t < ntiles; t++) {
        if (t + 1 < ntiles) CP_WAIT(1);
        else                CP_WAIT(0);
        __syncthreads();
        if (t + 2 < ntiles) issue_kv(t + 2);

        const uint32_t bu = kvb + (t % 3) * KVBUF_B;

        // ---- S = Q @ K^T : single pass, f32 acc ----
        float sacc[8][4];
#pragma unroll
        for (int nt = 0; nt < 8; nt++)
#pragma unroll
            for (int e = 0; e < 4; e++) sacc[nt][e] = 0.f;

#pragma unroll
        for (int nt = 0; nt < 8; nt++) {
            const uint32_t ka = bu + (uint32_t)((nt * 8 + (lane & 7)) * RS
                                                + (lane >> 3) * 16);
            uint32_t kf[8];
            ldsm_x4(kf, ka);
            ldsm_x4(kf + 4, ka + 64);
#pragma unroll
            for (int ck = 0; ck < 4; ck++)
                mma_f32(sacc[nt], qf[ck], &kf[ck * 2]);
        }

        // ---- causal mask (last two tiles) ----
        if (t >= ntiles - 2) {
            const int kv0 = t * 64;
#pragma unroll
            for (int nt = 0; nt < 8; nt++)
#pragma unroll
                for (int e = 0; e < 4; e++) {
                    const int key = kv0 + nt * 8 + 2 * (lane & 3) + (e & 1);
                    const int row = qrow + ((e & 2) ? 8 : 0);
                    if (key > row) sacc[nt][e] = -1e30f;
                }
        }

        // ---- online softmax ----
#pragma unroll
        for (int hh = 0; hh < 2; hh++) {
            float& mprev = hh ? m1 : m0;
            float& lsum  = hh ? l1 : l0;
            float mx = -1e30f;
#pragma unroll
            for (int nt = 0; nt < 8; nt++)
                mx = fmaxf(mx, fmaxf(sacc[nt][hh*2], sacc[nt][hh*2+1]));
            mx = fmaxf(mx, __shfl_xor_sync(0xffffffffu, mx, 1));
            mx = fmaxf(mx, __shfl_xor_sync(0xffffffffu, mx, 2));
            const float mn = fmaxf(mprev, mx);
            const float alpha = __expf(mprev - mn);
            mprev = mn;
            float ps = 0.f;
#pragma unroll
            for (int nt = 0; nt < 8; nt++) {
                const float p0 = __expf(sacc[nt][hh*2]   - mn);
                const float p1 = __expf(sacc[nt][hh*2+1] - mn);
                ps += p0 + p1;
                sacc[nt][hh*2]   = p0;
                sacc[nt][hh*2+1] = p1;
                oacc[nt][hh*2]   *= alpha;
                oacc[nt][hh*2+1] *= alpha;
            }
            lsum = lsum * alpha + ps;
        }

        // ---- pack P single fp16 into A fragments ----
        uint32_t ap[4][4];
#pragma unroll
        for (int ck = 0; ck < 4; ck++) {
            ap[ck][0] = pkf2(sacc[2*ck][0],   sacc[2*ck][1]);
            ap[ck][1] = pkf2(sacc[2*ck][2],   sacc[2*ck][3]);
            ap[ck][2] = pkf2(sacc[2*ck+1][0], sacc[2*ck+1][1]);
            ap[ck][3] = pkf2(sacc[2*ck+1][2], sacc[2*ck+1][3]);
        }

        // ---- O += P @ V : single pass, f32 acc ----
#pragma unroll
        for (int nt = 0; nt < 8; nt++) {
            const uint32_t va = bu + KVTILE_B + (uint32_t)(lane * RS + nt * 16);
            uint32_t vf[8];
            ldsm_x4t(vf, va);
            ldsm_x4t(vf + 4, va + 32 * RS);
#pragma unroll
            for (int ck = 0; ck < 4; ck++)
                mma_f32(oacc[nt], ap[ck], &vf[ck * 2]);
        }
    }

    // ---- finalize ----
    l0 += __shfl_xor_sync(0xffffffffu, l0, 1);
    l0 += __shfl_xor_sync(0xffffffffu, l0, 2);
    l1 += __shfl_xor_sync(0xffffffffu, l1, 1);
    l1 += __shfl_xor_sync(0xffffffffu, l1, 2);
    const float inv0 = 1.f / l0;
    const float inv1 = 1.f / l1;

#pragma unroll
    for (int nt = 0; nt < 8; nt++) {
        const int d = nt * 8 + 2 * (lane & 3);
#pragma unroll
        for (int hh = 0; hh < 2; hh++) {
            const int row = qrow + hh * 8;
            const float inv = hh ? inv1 : inv0;
            const size_t dst = ((size_t)(b * TT + row)) * CC + h * HD + d;
            *(uint32_t*)(g_ao + dst) = pkf2(oacc[nt][hh*2] * inv,
                                            oacc[nt][hh*2+1] * inv);
        }
    }
}

// ---------------------------------------------------------------------------
extern "C" void kernel_launch(void* const* d_in, const int* in_sizes, int n_in,
                              void* d_out, int out_size)
{
    const float* x  = (const float*)d_in[0];
    const float* Wq = (const float*)d_in[1];
    const float* bq = (const float*)d_in[2];
    const float* Wk = (const float*)d_in[3];
    const float* bk = (const float*)d_in[4];
    const float* Wv = (const float*)d_in[5];
    const float* bv = (const float*)d_in[6];
    const float* Wo = (const float*)d_in[7];
    const float* bo = (const float*)d_in[8];
    float* out = (float*)d_out;

    __half *xs, *q, *k, *v, *ao, *wt;
    cudaGetSymbolAddress((void**)&xs, g_x);
    cudaGetSymbolAddress((void**)&q,  g_q);
    cudaGetSymbolAddress((void**)&k,  g_k);
    cudaGetSymbolAddress((void**)&v,  g_v);
    cudaGetSymbolAddress((void**)&ao, g_ao);
    cudaGetSymbolAddress((void**)&wt, g_wt);

    static bool attr_set = false;
    if (!attr_set) {
        cudaFuncSetAttribute((const void*)mmagemm<0>,
                             cudaFuncAttributeMaxDynamicSharedMemorySize, GEMM_SMEM);
        cudaFuncSetAttribute((const void*)mmagemm<1>,
                             cudaFuncAttributeMaxDynamicSharedMemorySize, GEMM_SMEM);
        cudaFuncSetAttribute((const void*)flash6,
                             cudaFuncAttributeMaxDynamicSharedMemorySize, FL_SMEM);
        attr_set = true;
    }

    const int n4 = MROWS * CC / 4;
    castx<<<n4 / 256, 256>>>(x, xs);

    dim3 wgrid(CC / 32, CC / 32, 4);
    wsplit4<<<wgrid, 256>>>(Wq, Wk, Wv, Wo, wt);

    // fused QKV projection (N = 3072), 2-pass, single fp16 outputs
    dim3 qkv_grid(3 * CC / 128, MROWS / 128);   // (24, 32)
    mmagemm<1><<<qkv_grid, 256, GEMM_SMEM>>>(xs, wt, bq, bk, bv,
                                             nullptr, q, k, v);

    dim3 att_grid(TT / 128, HH, BB);
    flash6<<<att_grid, 256, FL_SMEM>>>(k, q, v);

    // output projection (N = 1024), 2-pass
    dim3 out_grid(CC / 128, MROWS / 128);       // (8, 32)
    mmagemm<0><<<out_grid, 256, GEMM_SMEM>>>(ao, wt + 6*(size_t)CC*CC,
                                             bo, nullptr, nullptr,
                                             out, nullptr, nullptr, nullptr);
}

// round 14
// speedup vs baseline: 2.6221x; 1.4207x over previous
#include <cuda_runtime.h>
#include <cuda_fp16.h>
#include <stdint.h>
#include <math.h>

// Problem constants
#define BB 2
#define TT 2048
#define CC 1024
#define HH 16
#define HD 64
#define MROWS (BB*TT)

// ---------------------------------------------------------------------------
// Scratch (allocation-free rule: __device__ globals) — all single fp16
// ---------------------------------------------------------------------------
__device__ __half g_x  [MROWS*CC];     // x fp16
__device__ __half g_q  [MROWS*CC];     // Q fp16, pre-scaled, [B,H,T,HD]
__device__ __half g_k  [MROWS*CC];     // K fp16, [B,H,T,HD]
__device__ __half g_v  [MROWS*CC];     // V fp16, [B,H,T,HD]
__device__ __half g_ao [MROWS*CC];     // attention out fp16, [B*T, C]
__device__ __half g_wt [4*CC*CC];      // [w][n][k]  (W^T, K-major, fp16)

// ---------------------------------------------------------------------------
// Warp-MMA helpers (base sm_80+ features)
// ---------------------------------------------------------------------------
__device__ __forceinline__ uint32_t s2u(const void* p) {
    uint32_t a;
    asm("{ .reg .u64 t; cvta.to.shared.u64 t, %1; cvt.u32.u64 %0, t; }"
        : "=r"(a) : "l"(p));
    return a;
}
__device__ __forceinline__ void ldsm_x4(uint32_t* r, uint32_t addr) {
    asm volatile("ldmatrix.sync.aligned.m8n8.x4.shared.b16 {%0,%1,%2,%3}, [%4];"
        : "=r"(r[0]), "=r"(r[1]), "=r"(r[2]), "=r"(r[3]) : "r"(addr));
}
__device__ __forceinline__ void ldsm_x4t(uint32_t* r, uint32_t addr) {
    asm volatile("ldmatrix.sync.aligned.m8n8.x4.trans.shared.b16 {%0,%1,%2,%3}, [%4];"
        : "=r"(r[0]), "=r"(r[1]), "=r"(r[2]), "=r"(r[3]) : "r"(addr));
}
__device__ __forceinline__ void mma_f32(float* c, const uint32_t* a, const uint32_t* b) {
    asm volatile(
        "mma.sync.aligned.m16n8k16.row.col.f32.f16.f16.f32 "
        "{%0,%1,%2,%3}, {%4,%5,%6,%7}, {%8,%9}, {%0,%1,%2,%3};"
        : "+f"(c[0]), "+f"(c[1]), "+f"(c[2]), "+f"(c[3])
        : "r"(a[0]), "r"(a[1]), "r"(a[2]), "r"(a[3]), "r"(b[0]), "r"(b[1]));
}
__device__ __forceinline__ void cpa16(uint32_t dst, const void* src) {
    asm volatile("cp.async.ca.shared.global [%0], [%1], 16;" :: "r"(dst), "l"(src));
}
#define CP_COMMIT() asm volatile("cp.async.commit_group;" ::: "memory")
#define CP_WAIT(n)  asm volatile("cp.async.wait_group %0;" :: "n"(n) : "memory")

__device__ __forceinline__ uint32_t pkf2(float a, float b) {
    __half2 t = __floats2half2_rn(a, b);
    return *(uint32_t*)&t;
}

// ---------------------------------------------------------------------------
// Prep kernels
// ---------------------------------------------------------------------------
__global__ void castx(const float* __restrict__ x, __half* __restrict__ hi)
{
    const int i = blockIdx.x * blockDim.x + threadIdx.x;
    float4 v = ((const float4*)x)[i];
    uint2 hw = { pkf2(v.x, v.y), pkf2(v.z, v.w) };
    ((uint2*)hi)[i] = hw;
}

// all 4 weight transpose+casts in one launch (z picks the weight)
__global__ __launch_bounds__(256)
void wcast4(const float* __restrict__ W0, const float* __restrict__ W1,
            const float* __restrict__ W2, const float* __restrict__ W3,
            __half* __restrict__ wt)
{
    __shared__ float t[32][33];
    const int wsel = blockIdx.z;
    const float* W = (wsel == 0) ? W0 : (wsel == 1) ? W1 : (wsel == 2) ? W2 : W3;
    __half* th = wt + (size_t)wsel * CC * CC;

    const int n0 = blockIdx.x * 32;
    const int k0 = blockIdx.y * 32;
    const int tx = threadIdx.x & 31;
    const int ty = threadIdx.x >> 5;
#pragma unroll
    for (int r = 0; r < 4; r++) {
        const int row = ty + r * 8;
        t[row][tx] = W[(size_t)(k0 + row) * CC + n0 + tx];
    }
    __syncthreads();
#pragma unroll
    for (int r = 0; r < 4; r++) {
        const int row = ty + r * 8;
        th[(size_t)(n0 + row) * CC + k0 + tx] = __float2half_rn(t[tx][row]);
    }
}

// ---------------------------------------------------------------------------
// mma.sync fp16 GEMM (128x128 CTA tile, 4 stages, f32-acc), single pass:
// Y = A*B + bias, A and B single fp16.
// MODE 1 (fused QKV): N=3072; q/k/v fp16 out, permuted; q scaled.
// MODE 0 (out proj):  N=1024; fp32 out.
// ---------------------------------------------------------------------------
#define KC 16
#define TSTRIDE 48
#define TILE_B (128*TSTRIDE)         // 6144
#define BUF_B  (2*TILE_B)            // 12288 (A, B)
#define GEMM_SMEM (4*BUF_B)          // 49152

template<int MODE>
__global__ __launch_bounds__(256, 2)
void mmagemm(const __half* __restrict__ Ah,
             const __half* __restrict__ Wt,
             const float* __restrict__ b0, const float* __restrict__ b1,
             const float* __restrict__ b2,
             float* __restrict__ Y,
             __half* __restrict__ Yq, __half* __restrict__ Yk,
             __half* __restrict__ Yv)
{
    extern __shared__ char dsm[];
    const uint32_t sb = s2u(dsm);

    const int tid = threadIdx.x;
    const int lane = tid & 31;
    const int wid = tid >> 5;
    const int warp_m = wid & 1;
    const int warp_n = wid >> 1;
    const int bm = blockIdx.y * 128;
    const int bn = blockIdx.x * 128;

    const int which = (MODE == 1) ? (bn >> 10) : 0;
    const int nw = bn & (CC - 1);
    const __half* Bm = Wt + (size_t)which * CC * CC;
    const float* bias = (MODE == 0) ? b0 : (which == 0) ? b0 : (which == 1) ? b1 : b2;
    const float scale = (MODE == 1 && which == 0) ? 0.125f : 1.0f;

    float acc[4][4][4];
#pragma unroll
    for (int i = 0; i < 4; i++)
#pragma unroll
        for (int j = 0; j < 4; j++)
#pragma unroll
            for (int q = 0; q < 4; q++) acc[i][j][q] = 0.f;

    // per-stage cp.async: 512 x 16B ops, 2 per thread (A tile, B tile)
    auto issue = [&](int c) {
        const int k0 = c * KC;
        const uint32_t bu = sb + (c & 3) * BUF_B;
#pragma unroll
        for (int i = 0; i < 2; i++) {
            const int j = i * 256 + tid;
            const int row = (j >> 1) & 127;
            const int seg = j & 1;
            const __half* s = (i == 0) ? Ah : Bm;
            const int rb = (i == 0) ? bm : nw;
            cpa16(bu + i * TILE_B + row * TSTRIDE + seg * 16,
                  s + (size_t)(rb + row) * CC + k0 + seg * 8);
        }
        CP_COMMIT();
    };

    issue(0); issue(1); issue(2);

    const uint32_t a_off = (uint32_t)((warp_m * 64 + (lane & 15)) * TSTRIDE
                                      + (lane >> 4) * 16);
    const uint32_t b_off = (uint32_t)((warp_n * 32 + ((lane >> 4) * 8) + (lane & 7)) * TSTRIDE
                                      + ((lane >> 3) & 1) * 16);

    for (int c = 0; c < 64; c++) {
        CP_WAIT(2);
        __syncthreads();
        if (c + 3 < 64) issue(c + 3);

        const uint32_t bu = sb + (c & 3) * BUF_B;
        uint32_t af[4][4];
        uint32_t bf[2][4];

#pragma unroll
        for (int p = 0; p < 2; p++)
            ldsm_x4(bf[p], bu + TILE_B + b_off + (uint32_t)(p * 16 * TSTRIDE));
#pragma unroll
        for (int mt = 0; mt < 4; mt++)
            ldsm_x4(af[mt], bu + a_off + (uint32_t)(mt * 16 * TSTRIDE));
#pragma unroll
        for (int mt = 0; mt < 4; mt++)
#pragma unroll
            for (int nt = 0; nt < 4; nt++)
                mma_f32(acc[mt][nt], af[mt], &bf[nt >> 1][(nt & 1) * 2]);
    }

#pragma unroll
    for (int mt = 0; mt < 4; mt++) {
#pragma unroll
        for (int nt = 0; nt < 4; nt++) {
            const int m0 = bm + warp_m * 64 + mt * 16 + (lane >> 2);
            const int nn = nw + warp_n * 32 + nt * 8 + 2 * (lane & 3);
            const float bb0 = __ldg(bias + nn);
            const float bb1 = __ldg(bias + nn + 1);
#pragma unroll
            for (int half = 0; half < 2; half++) {
                const int m = m0 + half * 8;
                const int bb = m >> 11;
                const int tt = m & (TT - 1);
                const float v0 = (acc[mt][nt][half * 2 + 0] + bb0) * scale;
                const float v1 = (acc[mt][nt][half * 2 + 1] + bb1) * scale;
                if (MODE == 0) {
                    float2 r; r.x = v0; r.y = v1;
                    *(float2*)(Y + (size_t)m * CC + nn) = r;
                } else {
                    const int h = nn >> 6;
                    const int d = nn & (HD - 1);
                    const size_t dst = (((size_t)bb * HH + h) * TT + tt) * HD + d;
                    __half* dp = (which == 0) ? Yq : (which == 1) ? Yk : Yv;
                    *(uint32_t*)(dp + dst) = pkf2(v0, v1);
                }
            }
        }
    }
}

// ---------------------------------------------------------------------------
// flash6: FA2 mma.sync causal attention, single-pass S and PV (unchanged).
// Q, K, V all single fp16 (Q pre-scaled). P single-rounded fp16. f32 acc.
// CTA: 128 q-rows, 8 warps x 16 rows. KV tiles of 64 keys, 3-stage pipeline.
// ---------------------------------------------------------------------------
#define RS 144
#define QTILE_B (128*RS)                 // 18432
#define KVTILE_B (64*RS)                 // 9216
#define KVBUF_B (2*KVTILE_B)             // 18432 (K, V)
#define FL_SMEM (QTILE_B + 3*KVBUF_B)    // 73728

__global__ __launch_bounds__(256, 1)
void flash6(const __half* __restrict__ K_, const __half* __restrict__ Q,
            const __half* __restrict__ V_)
{
    extern __shared__ char sm[];
    const uint32_t sb = s2u(sm);
    const uint32_t kvb = sb + QTILE_B;

    const int tid = threadIdx.x;
    const int lane = tid & 31;
    const int wid = tid >> 5;
    const int qt = blockIdx.x;
    const int h  = blockIdx.y;
    const int b  = blockIdx.z;
    const size_t head = ((size_t)b * HH + h) * TT * HD;

#pragma unroll
    for (int i = 0; i < 4; i++) {
        const int idx = i * 256 + tid;
        const int row = (idx >> 3) & 127;
        const int seg = idx & 7;
        cpa16(sb + row * RS + seg * 16,
              Q + head + (size_t)(qt * 128 + row) * HD + seg * 8);
    }
    CP_COMMIT();

    auto issue_kv = [&](int t) {
        const int kv0 = t * 64;
        const uint32_t bu = kvb + (t % 3) * KVBUF_B;
#pragma unroll
        for (int i = 0; i < 4; i++) {
            const int idx = i * 256 + tid;
            const int tile = idx >> 9;
            const int row = (idx >> 3) & 63;
            const int seg = idx & 7;
            const __half* src = (tile == 0) ? K_ : V_;
            cpa16(bu + tile * KVTILE_B + row * RS + seg * 16,
                  src + head + (size_t)(kv0 + row) * HD + seg * 8);
        }
        CP_COMMIT();
    };

    const int ntiles = (qt + 1) * 2;
    issue_kv(0);
    if (1 < ntiles) issue_kv(1);

    CP_WAIT(2);
    __syncthreads();

    uint32_t qf[4][4];
    {
        const uint32_t qaddr = sb + (uint32_t)((wid * 16 + (lane & 15)) * RS
                                               + (lane >> 4) * 16);
#pragma unroll
        for (int ck = 0; ck < 4; ck++)
            ldsm_x4(qf[ck], qaddr + ck * 32);
    }

    float m0 = -1e30f, m1 = -1e30f, l0 = 0.f, l1 = 0.f;
    float oacc[8][4];
#pragma unroll
    for (int nt = 0; nt < 8; nt++)
#pragma unroll
        for (int e = 0; e < 4; e++) oacc[nt][e] = 0.f;

    const int qrow = qt * 128 + wid * 16 + (lane >> 2);

    for (int t = 0; t < ntiles; t++) {
        if (t + 1 < ntiles) CP_WAIT(1);
        else                CP_WAIT(0);
        __syncthreads();
        if (t + 2 < ntiles) issue_kv(t + 2);

        const uint32_t bu = kvb + (t % 3) * KVBUF_B;

        float sacc[8][4];
#pragma unroll
        for (int nt = 0; nt < 8; nt++)
#pragma unroll
            for (int e = 0; e < 4; e++) sacc[nt][e] = 0.f;

#pragma unroll
        for (int nt = 0; nt < 8; nt++) {
            const uint32_t ka = bu + (uint32_t)((nt * 8 + (lane & 7)) * RS
                                                + (lane >> 3) * 16);
            uint32_t kf[8];
            ldsm_x4(kf, ka);
            ldsm_x4(kf + 4, ka + 64);
#pragma unroll
            for (int ck = 0; ck < 4; ck++)
                mma_f32(sacc[nt], qf[ck], &kf[ck * 2]);
        }

        if (t >= ntiles - 2) {
            const int kv0 = t * 64;
#pragma unroll
            for (int nt = 0; nt < 8; nt++)
#pragma unroll
                for (int e = 0; e < 4; e++) {
                    const int key = kv0 + nt * 8 + 2 * (lane & 3) + (e & 1);
                    const int row = qrow + ((e & 2) ? 8 : 0);
                    if (key > row) sacc[nt][e] = -1e30f;
                }
        }

#pragma unroll
        for (int hh = 0; hh < 2; hh++) {
            float& mprev = hh ? m1 : m0;
            float& lsum  = hh ? l1 : l0;
            float mx = -1e30f;
#pragma unroll
            for (int nt = 0; nt < 8; nt++)
                mx = fmaxf(mx, fmaxf(sacc[nt][hh*2], sacc[nt][hh*2+1]));
            mx = fmaxf(mx, __shfl_xor_sync(0xffffffffu, mx, 1));
            mx = fmaxf(mx, __shfl_xor_sync(0xffffffffu, mx, 2));
            const float mn = fmaxf(mprev, mx);
            const float alpha = __expf(mprev - mn);
            mprev = mn;
            float ps = 0.f;
#pragma unroll
            for (int nt = 0; nt < 8; nt++) {
                const float p0 = __expf(sacc[nt][hh*2]   - mn);
                const float p1 = __expf(sacc[nt][hh*2+1] - mn);
                ps += p0 + p1;
                sacc[nt][hh*2]   = p0;
                sacc[nt][hh*2+1] = p1;
                oacc[nt][hh*2]   *= alpha;
                oacc[nt][hh*2+1] *= alpha;
            }
            lsum = lsum * alpha + ps;
        }

        uint32_t ap[4][4];
#pragma unroll
        for (int ck = 0; ck < 4; ck++) {
            ap[ck][0] = pkf2(sacc[2*ck][0],   sacc[2*ck][1]);
            ap[ck][1] = pkf2(sacc[2*ck][2],   sacc[2*ck][3]);
            ap[ck][2] = pkf2(sacc[2*ck+1][0], sacc[2*ck+1][1]);
            ap[ck][3] = pkf2(sacc[2*ck+1][2], sacc[2*ck+1][3]);
        }

#pragma unroll
        for (int nt = 0; nt < 8; nt++) {
            const uint32_t va = bu + KVTILE_B + (uint32_t)(lane * RS + nt * 16);
            uint32_t vf[8];
            ldsm_x4t(vf, va);
            ldsm_x4t(vf + 4, va + 32 * RS);
#pragma unroll
            for (int ck = 0; ck < 4; ck++)
                mma_f32(oacc[nt], ap[ck], &vf[ck * 2]);
        }
    }

    l0 += __shfl_xor_sync(0xffffffffu, l0, 1);
    l0 += __shfl_xor_sync(0xffffffffu, l0, 2);
    l1 += __shfl_xor_sync(0xffffffffu, l1, 1);
    l1 += __shfl_xor_sync(0xffffffffu, l1, 2);
    const float inv0 = 1.f / l0;
    const float inv1 = 1.f / l1;

#pragma unroll
    for (int nt = 0; nt < 8; nt++) {
        const int d = nt * 8 + 2 * (lane & 3);
#pragma unroll
        for (int hh = 0; hh < 2; hh++) {
            const int row = qrow + hh * 8;
            const float inv = hh ? inv1 : inv0;
            const size_t dst = ((size_t)(b * TT + row)) * CC + h * HD + d;
            *(uint32_t*)(g_ao + dst) = pkf2(oacc[nt][hh*2] * inv,
                                            oacc[nt][hh*2+1] * inv);
        }
    }
}

// ---------------------------------------------------------------------------
extern "C" void kernel_launch(void* const* d_in, const int* in_sizes, int n_in,
                              void* d_out, int out_size)
{
    const float* x  = (const float*)d_in[0];
    const float* Wq = (const float*)d_in[1];
    const float* bq = (const float*)d_in[2];
    const float* Wk = (const float*)d_in[3];
    const float* bk = (const float*)d_in[4];
    const float* Wv = (const float*)d_in[5];
    const float* bv = (const float*)d_in[6];
    const float* Wo = (const float*)d_in[7];
    const float* bo = (const float*)d_in[8];
    float* out = (float*)d_out;

    __half *xs, *q, *k, *v, *ao, *wt;
    cudaGetSymbolAddress((void**)&xs, g_x);
    cudaGetSymbolAddress((void**)&q,  g_q);
    cudaGetSymbolAddress((void**)&k,  g_k);
    cudaGetSymbolAddress((void**)&v,  g_v);
    cudaGetSymbolAddress((void**)&ao, g_ao);
    cudaGetSymbolAddress((void**)&wt, g_wt);

    static bool attr_set = false;
    if (!attr_set) {
        cudaFuncSetAttribute((const void*)mmagemm<0>,
                             cudaFuncAttributeMaxDynamicSharedMemorySize, GEMM_SMEM);
        cudaFuncSetAttribute((const void*)mmagemm<1>,
                             cudaFuncAttributeMaxDynamicSharedMemorySize, GEMM_SMEM);
        cudaFuncSetAttribute((const void*)flash6,
                             cudaFuncAttributeMaxDynamicSharedMemorySize, FL_SMEM);
        attr_set = true;
    }

    const int n4 = MROWS * CC / 4;
    castx<<<n4 / 256, 256>>>(x, xs);

    dim3 wgrid(CC / 32, CC / 32, 4);
    wcast4<<<wgrid, 256>>>(Wq, Wk, Wv, Wo, wt);

    // fused QKV projection (N = 3072), 1-pass fp16
    dim3 qkv_grid(3 * CC / 128, MROWS / 128);   // (24, 32)
    mmagemm<1><<<qkv_grid, 256, GEMM_SMEM>>>(xs, wt, bq, bk, bv,
                                             nullptr, q, k, v);

    dim3 att_grid(TT / 128, HH, BB);
    flash6<<<att_grid, 256, FL_SMEM>>>(k, q, v);

    // output projection (N = 1024), 1-pass fp16
    dim3 out_grid(CC / 128, MROWS / 128);       // (8, 32)
    mmagemm<0><<<out_grid, 256, GEMM_SMEM>>>(ao, wt + 3*(size_t)CC*CC,
                                             bo, nullptr, nullptr,
                                             out, nullptr, nullptr, nullptr);
}

// round 15
// speedup vs baseline: 2.6702x; 1.0183x over previous
#include <cuda_runtime.h>
#include <cuda_fp16.h>
#include <stdint.h>
#include <math.h>

// Problem constants
#define BB 2
#define TT 2048
#define CC 1024
#define HH 16
#define HD 64
#define MROWS (BB*TT)

// ---------------------------------------------------------------------------
// Scratch (allocation-free rule: __device__ globals) — all single fp16
// ---------------------------------------------------------------------------
__device__ __half g_x  [MROWS*CC];     // x fp16
__device__ __half g_q  [MROWS*CC];     // Q fp16, pre-scaled by 0.125*log2e, [B,H,T,HD]
__device__ __half g_k  [MROWS*CC];     // K fp16, [B,H,T,HD]
__device__ __half g_v  [MROWS*CC];     // V fp16, [B,H,T,HD]
__device__ __half g_ao [MROWS*CC];     // attention out fp16, [B*T, C]
__device__ __half g_wt [4*CC*CC];      // [w][n][k]  (W^T, K-major, fp16)

// ---------------------------------------------------------------------------
// Warp-MMA helpers (base sm_80+ features)
// ---------------------------------------------------------------------------
__device__ __forceinline__ uint32_t s2u(const void* p) {
    uint32_t a;
    asm("{ .reg .u64 t; cvta.to.shared.u64 t, %1; cvt.u32.u64 %0, t; }"
        : "=r"(a) : "l"(p));
    return a;
}
__device__ __forceinline__ void ldsm_x4(uint32_t* r, uint32_t addr) {
    asm volatile("ldmatrix.sync.aligned.m8n8.x4.shared.b16 {%0,%1,%2,%3}, [%4];"
        : "=r"(r[0]), "=r"(r[1]), "=r"(r[2]), "=r"(r[3]) : "r"(addr));
}
__device__ __forceinline__ void ldsm_x4t(uint32_t* r, uint32_t addr) {
    asm volatile("ldmatrix.sync.aligned.m8n8.x4.trans.shared.b16 {%0,%1,%2,%3}, [%4];"
        : "=r"(r[0]), "=r"(r[1]), "=r"(r[2]), "=r"(r[3]) : "r"(addr));
}
__device__ __forceinline__ void mma_f32(float* c, const uint32_t* a, const uint32_t* b) {
    asm volatile(
        "mma.sync.aligned.m16n8k16.row.col.f32.f16.f16.f32 "
        "{%0,%1,%2,%3}, {%4,%5,%6,%7}, {%8,%9}, {%0,%1,%2,%3};"
        : "+f"(c[0]), "+f"(c[1]), "+f"(c[2]), "+f"(c[3])
        : "r"(a[0]), "r"(a[1]), "r"(a[2]), "r"(a[3]), "r"(b[0]), "r"(b[1]));
}
__device__ __forceinline__ void cpa16(uint32_t dst, const void* src) {
    asm volatile("cp.async.ca.shared.global [%0], [%1], 16;" :: "r"(dst), "l"(src));
}
#define CP_COMMIT() asm volatile("cp.async.commit_group;" ::: "memory")
#define CP_WAIT(n)  asm volatile("cp.async.wait_group %0;" :: "n"(n) : "memory")

__device__ __forceinline__ uint32_t pkf2(float a, float b) {
    __half2 t = __floats2half2_rn(a, b);
    return *(uint32_t*)&t;
}

// ---------------------------------------------------------------------------
// Fused prep kernel: z=0..3 -> weight transpose+cast; z=4 -> x cast.
// grid (32, 32, 5), 256 threads.
// ---------------------------------------------------------------------------
__global__ __launch_bounds__(256)
void prep(const float* __restrict__ x,
          const float* __restrict__ W0, const float* __restrict__ W1,
          const float* __restrict__ W2, const float* __restrict__ W3,
          __half* __restrict__ xs, __half* __restrict__ wt)
{
    if (blockIdx.z == 4) {
        const int blk = blockIdx.x + blockIdx.y * gridDim.x;   // 0..1023
#pragma unroll
        for (int r = 0; r < 4; r++) {
            const int idx = blk * 1024 + r * 256 + threadIdx.x;  // float4 idx
            float4 v = ((const float4*)x)[idx];
            uint2 hw = { pkf2(v.x, v.y), pkf2(v.z, v.w) };
            ((uint2*)xs)[idx] = hw;
        }
        return;
    }

    __shared__ float t[32][33];
    const int wsel = blockIdx.z;
    const float* W = (wsel == 0) ? W0 : (wsel == 1) ? W1 : (wsel == 2) ? W2 : W3;
    __half* th = wt + (size_t)wsel * CC * CC;

    const int n0 = blockIdx.x * 32;
    const int k0 = blockIdx.y * 32;
    const int tx = threadIdx.x & 31;
    const int ty = threadIdx.x >> 5;
#pragma unroll
    for (int r = 0; r < 4; r++) {
        const int row = ty + r * 8;
        t[row][tx] = W[(size_t)(k0 + row) * CC + n0 + tx];
    }
    __syncthreads();
#pragma unroll
    for (int r = 0; r < 4; r++) {
        const int row = ty + r * 8;
        th[(size_t)(n0 + row) * CC + k0 + tx] = __float2half_rn(t[tx][row]);
    }
}

// ---------------------------------------------------------------------------
// mma.sync fp16 GEMM (128x128 CTA tile, 4 stages, f32-acc), single pass.
// MODE 1 (fused QKV): N=3072; q/k/v fp16 out, permuted; q scaled by 0.125*log2e.
// MODE 0 (out proj):  N=1024; fp32 out.
// ---------------------------------------------------------------------------
#define KC 16
#define TSTRIDE 48
#define TILE_B (128*TSTRIDE)         // 6144
#define BUF_B  (2*TILE_B)            // 12288 (A, B)
#define GEMM_SMEM (4*BUF_B)          // 49152
#define QSCALE 0.1803368801111f      // 0.125 * log2(e)

template<int MODE>
__global__ __launch_bounds__(256, 2)
void mmagemm(const __half* __restrict__ Ah,
             const __half* __restrict__ Wt,
             const float* __restrict__ b0, const float* __restrict__ b1,
             const float* __restrict__ b2,
             float* __restrict__ Y,
             __half* __restrict__ Yq, __half* __restrict__ Yk,
             __half* __restrict__ Yv)
{
    extern __shared__ char dsm[];
    const uint32_t sb = s2u(dsm);

    const int tid = threadIdx.x;
    const int lane = tid & 31;
    const int wid = tid >> 5;
    const int warp_m = wid & 1;
    const int warp_n = wid >> 1;
    const int bm = blockIdx.y * 128;
    const int bn = blockIdx.x * 128;

    const int which = (MODE == 1) ? (bn >> 10) : 0;
    const int nw = bn & (CC - 1);
    const __half* Bm = Wt + (size_t)which * CC * CC;
    const float* bias = (MODE == 0) ? b0 : (which == 0) ? b0 : (which == 1) ? b1 : b2;
    const float scale = (MODE == 1 && which == 0) ? QSCALE : 1.0f;

    float acc[4][4][4];
#pragma unroll
    for (int i = 0; i < 4; i++)
#pragma unroll
        for (int j = 0; j < 4; j++)
#pragma unroll
            for (int q = 0; q < 4; q++) acc[i][j][q] = 0.f;

    auto issue = [&](int c) {
        const int k0 = c * KC;
        const uint32_t bu = sb + (c & 3) * BUF_B;
#pragma unroll
        for (int i = 0; i < 2; i++) {
            const int j = i * 256 + tid;
            const int row = (j >> 1) & 127;
            const int seg = j & 1;
            const __half* s = (i == 0) ? Ah : Bm;
            const int rb = (i == 0) ? bm : nw;
            cpa16(bu + i * TILE_B + row * TSTRIDE + seg * 16,
                  s + (size_t)(rb + row) * CC + k0 + seg * 8);
        }
        CP_COMMIT();
    };

    issue(0); issue(1); issue(2);

    const uint32_t a_off = (uint32_t)((warp_m * 64 + (lane & 15)) * TSTRIDE
                                      + (lane >> 4) * 16);
    const uint32_t b_off = (uint32_t)((warp_n * 32 + ((lane >> 4) * 8) + (lane & 7)) * TSTRIDE
                                      + ((lane >> 3) & 1) * 16);

    for (int c = 0; c < 64; c++) {
        CP_WAIT(2);
        __syncthreads();
        if (c + 3 < 64) issue(c + 3);

        const uint32_t bu = sb + (c & 3) * BUF_B;
        uint32_t af[4][4];
        uint32_t bf[2][4];

#pragma unroll
        for (int p = 0; p < 2; p++)
            ldsm_x4(bf[p], bu + TILE_B + b_off + (uint32_t)(p * 16 * TSTRIDE));
#pragma unroll
        for (int mt = 0; mt < 4; mt++)
            ldsm_x4(af[mt], bu + a_off + (uint32_t)(mt * 16 * TSTRIDE));
#pragma unroll
        for (int mt = 0; mt < 4; mt++)
#pragma unroll
            for (int nt = 0; nt < 4; nt++)
                mma_f32(acc[mt][nt], af[mt], &bf[nt >> 1][(nt & 1) * 2]);
    }

#pragma unroll
    for (int mt = 0; mt < 4; mt++) {
#pragma unroll
        for (int nt = 0; nt < 4; nt++) {
            const int m0 = bm + warp_m * 64 + mt * 16 + (lane >> 2);
            const int nn = nw + warp_n * 32 + nt * 8 + 2 * (lane & 3);
            const float bb0 = __ldg(bias + nn);
            const float bb1 = __ldg(bias + nn + 1);
#pragma unroll
            for (int half = 0; half < 2; half++) {
                const int m = m0 + half * 8;
                const int bb = m >> 11;
                const int tt = m & (TT - 1);
                const float v0 = (acc[mt][nt][half * 2 + 0] + bb0) * scale;
                const float v1 = (acc[mt][nt][half * 2 + 1] + bb1) * scale;
                if (MODE == 0) {
                    float2 r; r.x = v0; r.y = v1;
                    *(float2*)(Y + (size_t)m * CC + nn) = r;
                } else {
                    const int h = nn >> 6;
                    const int d = nn & (HD - 1);
                    const size_t dst = (((size_t)bb * HH + h) * TT + tt) * HD + d;
                    __half* dp = (which == 0) ? Yq : (which == 1) ? Yk : Yv;
                    *(uint32_t*)(dp + dst) = pkf2(v0, v1);
                }
            }
        }
    }
}

// ---------------------------------------------------------------------------
// flash7: FA2 mma.sync causal attention (fp16 in, f32 acc), base-2 softmax.
// Q pre-scaled by 0.125*log2e so p = exp2(s - m). Tricks:
//  - reversed qt order (heavy CTAs first)
//  - last-tile skip for fully-masked warps 0..3
//  - warp-uniform skip of oacc rescale when no row max changed
// CTA: 128 q-rows, 8 warps x 16 rows. KV tiles of 64 keys, 3-stage pipeline.
// ---------------------------------------------------------------------------
#define RS 144
#define QTILE_B (128*RS)                 // 18432
#define KVTILE_B (64*RS)                 // 9216
#define KVBUF_B (2*KVTILE_B)             // 18432 (K, V)
#define FL_SMEM (QTILE_B + 3*KVBUF_B)    // 73728

__global__ __launch_bounds__(256, 1)
void flash7(const __half* __restrict__ K_, const __half* __restrict__ Q,
            const __half* __restrict__ V_)
{
    extern __shared__ char sm[];
    const uint32_t sb = s2u(sm);
    const uint32_t kvb = sb + QTILE_B;

    const int tid = threadIdx.x;
    const int lane = tid & 31;
    const int wid = tid >> 5;
    const int qt = (gridDim.x - 1) - blockIdx.x;   // heavy CTAs first
    const int h  = blockIdx.y;
    const int b  = blockIdx.z;
    const size_t head = ((size_t)b * HH + h) * TT * HD;

#pragma unroll
    for (int i = 0; i < 4; i++) {
        const int idx = i * 256 + tid;
        const int row = (idx >> 3) & 127;
        const int seg = idx & 7;
        cpa16(sb + row * RS + seg * 16,
              Q + head + (size_t)(qt * 128 + row) * HD + seg * 8);
    }
    CP_COMMIT();

    auto issue_kv = [&](int t) {
        const int kv0 = t * 64;
        const uint32_t bu = kvb + (t % 3) * KVBUF_B;
#pragma unroll
        for (int i = 0; i < 4; i++) {
            const int idx = i * 256 + tid;
            const int tile = idx >> 9;
            const int row = (idx >> 3) & 63;
            const int seg = idx & 7;
            const __half* src = (tile == 0) ? K_ : V_;
            cpa16(bu + tile * KVTILE_B + row * RS + seg * 16,
                  src + head + (size_t)(kv0 + row) * HD + seg * 8);
        }
        CP_COMMIT();
    };

    const int ntiles = (qt + 1) * 2;
    issue_kv(0);
    if (1 < ntiles) issue_kv(1);

    CP_WAIT(2);
    __syncthreads();

    uint32_t qf[4][4];
    {
        const uint32_t qaddr = sb + (uint32_t)((wid * 16 + (lane & 15)) * RS
                                               + (lane >> 4) * 16);
#pragma unroll
        for (int ck = 0; ck < 4; ck++)
            ldsm_x4(qf[ck], qaddr + ck * 32);
    }

    float m0 = -1e30f, m1 = -1e30f, l0 = 0.f, l1 = 0.f;
    float oacc[8][4];
#pragma unroll
    for (int nt = 0; nt < 8; nt++)
#pragma unroll
        for (int e = 0; e < 4; e++) oacc[nt][e] = 0.f;

    const int qrow = qt * 128 + wid * 16 + (lane >> 2);

    for (int t = 0; t < ntiles; t++) {
        if (t + 1 < ntiles) CP_WAIT(1);
        else                CP_WAIT(0);
        __syncthreads();
        if (t + 2 < ntiles) issue_kv(t + 2);

        // last KV tile covers keys >= qt*128+64, fully masked for warps 0..3
        if ((t == ntiles - 1) && (wid < 4)) continue;

        const uint32_t bu = kvb + (t % 3) * KVBUF_B;

        // ---- S(log2-domain) = Q @ K^T : single pass, f32 acc ----
        float sacc[8][4];
#pragma unroll
        for (int nt = 0; nt < 8; nt++)
#pragma unroll
            for (int e = 0; e < 4; e++) sacc[nt][e] = 0.f;

#pragma unroll
        for (int nt = 0; nt < 8; nt++) {
            const uint32_t ka = bu + (uint32_t)((nt * 8 + (lane & 7)) * RS
                                                + (lane >> 3) * 16);
            uint32_t kf[8];
            ldsm_x4(kf, ka);
            ldsm_x4(kf + 4, ka + 64);
#pragma unroll
            for (int ck = 0; ck < 4; ck++)
                mma_f32(sacc[nt], qf[ck], &kf[ck * 2]);
        }

        // ---- causal mask (last two tiles) ----
        if (t >= ntiles - 2) {
            const int kv0 = t * 64;
#pragma unroll
            for (int nt = 0; nt < 8; nt++)
#pragma unroll
                for (int e = 0; e < 4; e++) {
                    const int key = kv0 + nt * 8 + 2 * (lane & 3) + (e & 1);
                    const int row = qrow + ((e & 2) ? 8 : 0);
                    if (key > row) sacc[nt][e] = -1e30f;
                }
        }

        // ---- online softmax (base-2) ----
#pragma unroll
        for (int hh = 0; hh < 2; hh++) {
            float& mprev = hh ? m1 : m0;
            float& lsum  = hh ? l1 : l0;
            float mx = -1e30f;
#pragma unroll
            for (int nt = 0; nt < 8; nt++)
                mx = fmaxf(mx, fmaxf(sacc[nt][hh*2], sacc[nt][hh*2+1]));
            mx = fmaxf(mx, __shfl_xor_sync(0xffffffffu, mx, 1));
            mx = fmaxf(mx, __shfl_xor_sync(0xffffffffu, mx, 2));
            const float mn = fmaxf(mprev, mx);

            // rescale only if any row max in the warp changed (warp-uniform)
            if (__any_sync(0xffffffffu, mn > mprev)) {
                const float alpha = exp2f(mprev - mn);
                lsum *= alpha;
#pragma unroll
                for (int nt = 0; nt < 8; nt++) {
                    oacc[nt][hh*2]   *= alpha;
                    oacc[nt][hh*2+1] *= alpha;
                }
                mprev = mn;
            }

            float ps = 0.f;
#pragma unroll
            for (int nt = 0; nt < 8; nt++) {
                const float p0 = exp2f(sacc[nt][hh*2]   - mprev);
                const float p1 = exp2f(sacc[nt][hh*2+1] - mprev);
                ps += p0 + p1;
                sacc[nt][hh*2]   = p0;
                sacc[nt][hh*2+1] = p1;
            }
            lsum += ps;
        }

        // ---- pack P fp16 into A fragments ----
        uint32_t ap[4][4];
#pragma unroll
        for (int ck = 0; ck < 4; ck++) {
            ap[ck][0] = pkf2(sacc[2*ck][0],   sacc[2*ck][1]);
            ap[ck][1] = pkf2(sacc[2*ck][2],   sacc[2*ck][3]);
            ap[ck][2] = pkf2(sacc[2*ck+1][0], sacc[2*ck+1][1]);
            ap[ck][3] = pkf2(sacc[2*ck+1][2], sacc[2*ck+1][3]);
        }

        // ---- O += P @ V : single pass, f32 acc ----
#pragma unroll
        for (int nt = 0; nt < 8; nt++) {
            const uint32_t va = bu + KVTILE_B + (uint32_t)(lane * RS + nt * 16);
            uint32_t vf[8];
            ldsm_x4t(vf, va);
            ldsm_x4t(vf + 4, va + 32 * RS);
#pragma unroll
            for (int ck = 0; ck < 4; ck++)
                mma_f32(oacc[nt], ap[ck], &vf[ck * 2]);
        }
    }

    // ---- finalize ----
    l0 += __shfl_xor_sync(0xffffffffu, l0, 1);
    l0 += __shfl_xor_sync(0xffffffffu, l0, 2);
    l1 += __shfl_xor_sync(0xffffffffu, l1, 1);
    l1 += __shfl_xor_sync(0xffffffffu, l1, 2);
    const float inv0 = 1.f / l0;
    const float inv1 = 1.f / l1;

#pragma unroll
    for (int nt = 0; nt < 8; nt++) {
        const int d = nt * 8 + 2 * (lane & 3);
#pragma unroll
        for (int hh = 0; hh < 2; hh++) {
            const int row = qrow + hh * 8;
            const float inv = hh ? inv1 : inv0;
            const size_t dst = ((size_t)(b * TT + row)) * CC + h * HD + d;
            *(uint32_t*)(g_ao + dst) = pkf2(oacc[nt][hh*2] * inv,
                                            oacc[nt][hh*2+1] * inv);
        }
    }
}

// ---------------------------------------------------------------------------
extern "C" void kernel_launch(void* const* d_in, const int* in_sizes, int n_in,
                              void* d_out, int out_size)
{
    const float* x  = (const float*)d_in[0];
    const float* Wq = (const float*)d_in[1];
    const float* bq = (const float*)d_in[2];
    const float* Wk = (const float*)d_in[3];
    const float* bk = (const float*)d_in[4];
    const float* Wv = (const float*)d_in[5];
    const float* bv = (const float*)d_in[6];
    const float* Wo = (const float*)d_in[7];
    const float* bo = (const float*)d_in[8];
    float* out = (float*)d_out;

    __half *xs, *q, *k, *v, *ao, *wt;
    cudaGetSymbolAddress((void**)&xs, g_x);
    cudaGetSymbolAddress((void**)&q,  g_q);
    cudaGetSymbolAddress((void**)&k,  g_k);
    cudaGetSymbolAddress((void**)&v,  g_v);
    cudaGetSymbolAddress((void**)&ao, g_ao);
    cudaGetSymbolAddress((void**)&wt, g_wt);

    static bool attr_set = false;
    if (!attr_set) {
        cudaFuncSetAttribute((const void*)mmagemm<0>,
                             cudaFuncAttributeMaxDynamicSharedMemorySize, GEMM_SMEM);
        cudaFuncSetAttribute((const void*)mmagemm<1>,
                             cudaFuncAttributeMaxDynamicSharedMemorySize, GEMM_SMEM);
        cudaFuncSetAttribute((const void*)flash7,
                             cudaFuncAttributeMaxDynamicSharedMemorySize, FL_SMEM);
        attr_set = true;
    }

    // fused prep: 4 weight casts + x cast
    dim3 pgrid(CC / 32, CC / 32, 5);
    prep<<<pgrid, 256>>>(x, Wq, Wk, Wv, Wo, xs, wt);

    // fused QKV projection (N = 3072), 1-pass fp16
    dim3 qkv_grid(3 * CC / 128, MROWS / 128);   // (24, 32)
    mmagemm<1><<<qkv_grid, 256, GEMM_SMEM>>>(xs, wt, bq, bk, bv,
                                             nullptr, q, k, v);

    dim3 att_grid(TT / 128, HH, BB);
    flash7<<<att_grid, 256, FL_SMEM>>>(k, q, v);

    // output projection (N = 1024), 1-pass fp16
    dim3 out_grid(CC / 128, MROWS / 128);       // (8, 32)
    mmagemm<0><<<out_grid, 256, GEMM_SMEM>>>(ao, wt + 3*(size_t)CC*CC,
                                             bo, nullptr, nullptr,
                                             out, nullptr, nullptr, nullptr);
}

// round 16
// speedup vs baseline: 2.8026x; 1.0496x over previous
#include <cuda_runtime.h>
#include <cuda_fp16.h>
#include <stdint.h>
#include <math.h>

// Problem constants
#define BB 2
#define TT 2048
#define CC 1024
#define HH 16
#define HD 64
#define MROWS (BB*TT)

// ---------------------------------------------------------------------------
// Scratch (allocation-free rule: __device__ globals) — all single fp16
// ---------------------------------------------------------------------------
__device__ __half g_x  [MROWS*CC];     // x fp16
__device__ __half g_q  [MROWS*CC];     // Q fp16, pre-scaled by 0.125*log2e, [B,H,T,HD]
__device__ __half g_k  [MROWS*CC];     // K fp16, [B,H,T,HD]
__device__ __half g_v  [MROWS*CC];     // V fp16, [B,H,T,HD]
__device__ __half g_ao [MROWS*CC];     // attention out fp16, [B*T, C]
__device__ __half g_wt [4*CC*CC];      // [w][n][k]  (W^T, K-major, fp16)

// ---------------------------------------------------------------------------
// Warp-MMA helpers (base sm_80+ features)
// ---------------------------------------------------------------------------
__device__ __forceinline__ uint32_t s2u(const void* p) {
    uint32_t a;
    asm("{ .reg .u64 t; cvta.to.shared.u64 t, %1; cvt.u32.u64 %0, t; }"
        : "=r"(a) : "l"(p));
    return a;
}
__device__ __forceinline__ void ldsm_x4(uint32_t* r, uint32_t addr) {
    asm volatile("ldmatrix.sync.aligned.m8n8.x4.shared.b16 {%0,%1,%2,%3}, [%4];"
        : "=r"(r[0]), "=r"(r[1]), "=r"(r[2]), "=r"(r[3]) : "r"(addr));
}
__device__ __forceinline__ void ldsm_x4t(uint32_t* r, uint32_t addr) {
    asm volatile("ldmatrix.sync.aligned.m8n8.x4.trans.shared.b16 {%0,%1,%2,%3}, [%4];"
        : "=r"(r[0]), "=r"(r[1]), "=r"(r[2]), "=r"(r[3]) : "r"(addr));
}
__device__ __forceinline__ void mma_f32(float* c, const uint32_t* a, const uint32_t* b) {
    asm volatile(
        "mma.sync.aligned.m16n8k16.row.col.f32.f16.f16.f32 "
        "{%0,%1,%2,%3}, {%4,%5,%6,%7}, {%8,%9}, {%0,%1,%2,%3};"
        : "+f"(c[0]), "+f"(c[1]), "+f"(c[2]), "+f"(c[3])
        : "r"(a[0]), "r"(a[1]), "r"(a[2]), "r"(a[3]), "r"(b[0]), "r"(b[1]));
}
__device__ __forceinline__ void cpa16(uint32_t dst, const void* src) {
    asm volatile("cp.async.ca.shared.global [%0], [%1], 16;" :: "r"(dst), "l"(src));
}
#define CP_COMMIT() asm volatile("cp.async.commit_group;" ::: "memory")
#define CP_WAIT(n)  asm volatile("cp.async.wait_group %0;" :: "n"(n) : "memory")

__device__ __forceinline__ uint32_t pkf2(float a, float b) {
    __half2 t = __floats2half2_rn(a, b);
    return *(uint32_t*)&t;
}

// ---------------------------------------------------------------------------
// Fused prep kernel: z=0..3 -> weight transpose+cast; z=4 -> x cast.
// ---------------------------------------------------------------------------
__global__ __launch_bounds__(256)
void prep(const float* __restrict__ x,
          const float* __restrict__ W0, const float* __restrict__ W1,
          const float* __restrict__ W2, const float* __restrict__ W3,
          __half* __restrict__ xs, __half* __restrict__ wt)
{
    if (blockIdx.z == 4) {
        const int blk = blockIdx.x + blockIdx.y * gridDim.x;
#pragma unroll
        for (int r = 0; r < 4; r++) {
            const int idx = blk * 1024 + r * 256 + threadIdx.x;
            float4 v = ((const float4*)x)[idx];
            uint2 hw = { pkf2(v.x, v.y), pkf2(v.z, v.w) };
            ((uint2*)xs)[idx] = hw;
        }
        return;
    }

    __shared__ float t[32][33];
    const int wsel = blockIdx.z;
    const float* W = (wsel == 0) ? W0 : (wsel == 1) ? W1 : (wsel == 2) ? W2 : W3;
    __half* th = wt + (size_t)wsel * CC * CC;

    const int n0 = blockIdx.x * 32;
    const int k0 = blockIdx.y * 32;
    const int tx = threadIdx.x & 31;
    const int ty = threadIdx.x >> 5;
#pragma unroll
    for (int r = 0; r < 4; r++) {
        const int row = ty + r * 8;
        t[row][tx] = W[(size_t)(k0 + row) * CC + n0 + tx];
    }
    __syncthreads();
#pragma unroll
    for (int r = 0; r < 4; r++) {
        const int row = ty + r * 8;
        th[(size_t)(n0 + row) * CC + k0 + tx] = __float2half_rn(t[tx][row]);
    }
}

// ---------------------------------------------------------------------------
// mma.sync fp16 GEMM (128x128 CTA tile, f32-acc), single pass.
// K-chunks of 32, 4-stage cp.async pipeline (one sync per 32 K).
// MODE 1 (fused QKV): N=3072; q/k/v fp16 out, permuted; q scaled by 0.125*log2e.
// MODE 0 (out proj):  N=1024; fp32 out.
// ---------------------------------------------------------------------------
#define KC 32
#define NCHUNK (CC/KC)               // 32
#define TS2 80                       // row stride bytes (64B data + 16 pad)
#define TILE2_B (128*TS2)            // 10240
#define BUF2_B  (2*TILE2_B)          // 20480 (A, B)
#define GEMM_SMEM (4*BUF2_B)         // 81920
#define QSCALE 0.1803368801111f      // 0.125 * log2(e)

template<int MODE>
__global__ __launch_bounds__(256, 2)
void mmagemm(const __half* __restrict__ Ah,
             const __half* __restrict__ Wt,
             const float* __restrict__ b0, const float* __restrict__ b1,
             const float* __restrict__ b2,
             float* __restrict__ Y,
             __half* __restrict__ Yq, __half* __restrict__ Yk,
             __half* __restrict__ Yv)
{
    extern __shared__ char dsm[];
    const uint32_t sb = s2u(dsm);

    const int tid = threadIdx.x;
    const int lane = tid & 31;
    const int wid = tid >> 5;
    const int warp_m = wid & 1;
    const int warp_n = wid >> 1;
    const int bm = blockIdx.y * 128;
    const int bn = blockIdx.x * 128;

    const int which = (MODE == 1) ? (bn >> 10) : 0;
    const int nw = bn & (CC - 1);
    const __half* Bm = Wt + (size_t)which * CC * CC;
    const float* bias = (MODE == 0) ? b0 : (which == 0) ? b0 : (which == 1) ? b1 : b2;
    const float scale = (MODE == 1 && which == 0) ? QSCALE : 1.0f;

    float acc[4][4][4];
#pragma unroll
    for (int i = 0; i < 4; i++)
#pragma unroll
        for (int j = 0; j < 4; j++)
#pragma unroll
            for (int q = 0; q < 4; q++) acc[i][j][q] = 0.f;

    // per-stage cp.async: A 128x64B + B 128x64B = 1024 x 16B ops, 4 per thread
    auto issue = [&](int c) {
        const int k0 = c * KC;
        const uint32_t bu = sb + (c & 3) * BUF2_B;
#pragma unroll
        for (int i = 0; i < 2; i++) {
#pragma unroll
            for (int o = 0; o < 2; o++) {
                const int j = o * 256 + tid;      // 0..511
                const int row = j >> 2;
                const int seg = j & 3;
                const __half* s = (i == 0) ? Ah : Bm;
                const int rb = (i == 0) ? bm : nw;
                cpa16(bu + i * TILE2_B + row * TS2 + seg * 16,
                      s + (size_t)(rb + row) * CC + k0 + seg * 8);
            }
        }
        CP_COMMIT();
    };

    issue(0); issue(1); issue(2);

    const uint32_t a_off = (uint32_t)((warp_m * 64 + (lane & 15)) * TS2
                                      + (lane >> 4) * 16);
    const uint32_t b_off = (uint32_t)((warp_n * 32 + ((lane >> 4) * 8) + (lane & 7)) * TS2
                                      + ((lane >> 3) & 1) * 16);

    for (int c = 0; c < NCHUNK; c++) {
        const int rem = NCHUNK - 1 - c;
        if (rem >= 2)      CP_WAIT(2);
        else if (rem == 1) CP_WAIT(1);
        else               CP_WAIT(0);
        __syncthreads();
        if (c + 3 < NCHUNK) issue(c + 3);

        const uint32_t bu = sb + (c & 3) * BUF2_B;

#pragma unroll
        for (int kk = 0; kk < 2; kk++) {          // two K=16 halves per chunk
            const uint32_t koff = (uint32_t)(kk * 32);
            uint32_t af[4][4];
            uint32_t bf[2][4];
#pragma unroll
            for (int p = 0; p < 2; p++)
                ldsm_x4(bf[p], bu + TILE2_B + b_off + koff
                               + (uint32_t)(p * 16 * TS2));
#pragma unroll
            for (int mt = 0; mt < 4; mt++)
                ldsm_x4(af[mt], bu + a_off + koff + (uint32_t)(mt * 16 * TS2));
#pragma unroll
            for (int mt = 0; mt < 4; mt++)
#pragma unroll
                for (int nt = 0; nt < 4; nt++)
                    mma_f32(acc[mt][nt], af[mt], &bf[nt >> 1][(nt & 1) * 2]);
        }
    }

#pragma unroll
    for (int mt = 0; mt < 4; mt++) {
#pragma unroll
        for (int nt = 0; nt < 4; nt++) {
            const int m0 = bm + warp_m * 64 + mt * 16 + (lane >> 2);
            const int nn = nw + warp_n * 32 + nt * 8 + 2 * (lane & 3);
            const float bb0 = __ldg(bias + nn);
            const float bb1 = __ldg(bias + nn + 1);
#pragma unroll
            for (int half = 0; half < 2; half++) {
                const int m = m0 + half * 8;
                const int bb = m >> 11;
                const int tt = m & (TT - 1);
                const float v0 = (acc[mt][nt][half * 2 + 0] + bb0) * scale;
                const float v1 = (acc[mt][nt][half * 2 + 1] + bb1) * scale;
                if (MODE == 0) {
                    float2 r; r.x = v0; r.y = v1;
                    *(float2*)(Y + (size_t)m * CC + nn) = r;
                } else {
                    const int h = nn >> 6;
                    const int d = nn & (HD - 1);
                    const size_t dst = (((size_t)bb * HH + h) * TT + tt) * HD + d;
                    __half* dp = (which == 0) ? Yq : (which == 1) ? Yk : Yv;
                    *(uint32_t*)(dp + dst) = pkf2(v0, v1);
                }
            }
        }
    }
}

// ---------------------------------------------------------------------------
// flash8: FA2 mma.sync causal attention (fp16 in, f32 acc), base-2 softmax,
// 4-stage KV pipeline with prefetch depth 3.
//  - reversed qt order (heavy CTAs first)
//  - last-tile skip for fully-masked warps 0..3
//  - warp-uniform skip of oacc rescale when no row max changed
// CTA: 128 q-rows, 8 warps x 16 rows. KV tiles of 64 keys.
// ---------------------------------------------------------------------------
#define RS 144
#define QTILE_B (128*RS)                 // 18432
#define KVTILE_B (64*RS)                 // 9216
#define KVBUF_B (2*KVTILE_B)             // 18432 (K, V)
#define FL_SMEM (QTILE_B + 4*KVBUF_B)    // 92160

__global__ __launch_bounds__(256, 1)
void flash8(const __half* __restrict__ K_, const __half* __restrict__ Q,
            const __half* __restrict__ V_)
{
    extern __shared__ char sm[];
    const uint32_t sb = s2u(sm);
    const uint32_t kvb = sb + QTILE_B;

    const int tid = threadIdx.x;
    const int lane = tid & 31;
    const int wid = tid >> 5;
    const int qt = (gridDim.x - 1) - blockIdx.x;   // heavy CTAs first
    const int h  = blockIdx.y;
    const int b  = blockIdx.z;
    const size_t head = ((size_t)b * HH + h) * TT * HD;

#pragma unroll
    for (int i = 0; i < 4; i++) {
        const int idx = i * 256 + tid;
        const int row = (idx >> 3) & 127;
        const int seg = idx & 7;
        cpa16(sb + row * RS + seg * 16,
              Q + head + (size_t)(qt * 128 + row) * HD + seg * 8);
    }
    CP_COMMIT();

    auto issue_kv = [&](int t) {
        const int kv0 = t * 64;
        const uint32_t bu = kvb + (t & 3) * KVBUF_B;
#pragma unroll
        for (int i = 0; i < 4; i++) {
            const int idx = i * 256 + tid;
            const int tile = idx >> 9;
            const int row = (idx >> 3) & 63;
            const int seg = idx & 7;
            const __half* src = (tile == 0) ? K_ : V_;
            cpa16(bu + tile * KVTILE_B + row * RS + seg * 16,
                  src + head + (size_t)(kv0 + row) * HD + seg * 8);
        }
        CP_COMMIT();
    };

    const int ntiles = (qt + 1) * 2;   // always >= 2
    issue_kv(0);
    issue_kv(1);
    if (2 < ntiles) issue_kv(2);

    // wait for Q (allow the issued KV groups to remain pending)
    if (2 < ntiles) CP_WAIT(3);
    else            CP_WAIT(2);
    __syncthreads();

    uint32_t qf[4][4];
    {
        const uint32_t qaddr = sb + (uint32_t)((wid * 16 + (lane & 15)) * RS
                                               + (lane >> 4) * 16);
#pragma unroll
        for (int ck = 0; ck < 4; ck++)
            ldsm_x4(qf[ck], qaddr + ck * 32);
    }

    float m0 = -1e30f, m1 = -1e30f, l0 = 0.f, l1 = 0.f;
    float oacc[8][4];
#pragma unroll
    for (int nt = 0; nt < 8; nt++)
#pragma unroll
        for (int e = 0; e < 4; e++) oacc[nt][e] = 0.f;

    const int qrow = qt * 128 + wid * 16 + (lane >> 2);

    for (int t = 0; t < ntiles; t++) {
        const int rem = ntiles - 1 - t;
        if (rem >= 2)      CP_WAIT(2);
        else if (rem == 1) CP_WAIT(1);
        else               CP_WAIT(0);
        __syncthreads();
        if (t + 3 < ntiles) issue_kv(t + 3);

        // last KV tile covers keys >= qt*128+64, fully masked for warps 0..3
        if ((t == ntiles - 1) && (wid < 4)) continue;

        const uint32_t bu = kvb + (t & 3) * KVBUF_B;

        // ---- S(log2-domain) = Q @ K^T : single pass, f32 acc ----
        float sacc[8][4];
#pragma unroll
        for (int nt = 0; nt < 8; nt++)
#pragma unroll
            for (int e = 0; e < 4; e++) sacc[nt][e] = 0.f;

#pragma unroll
        for (int nt = 0; nt < 8; nt++) {
            const uint32_t ka = bu + (uint32_t)((nt * 8 + (lane & 7)) * RS
                                                + (lane >> 3) * 16);
            uint32_t kf[8];
            ldsm_x4(kf, ka);
            ldsm_x4(kf + 4, ka + 64);
#pragma unroll
            for (int ck = 0; ck < 4; ck++)
                mma_f32(sacc[nt], qf[ck], &kf[ck * 2]);
        }

        // ---- causal mask (last two tiles) ----
        if (t >= ntiles - 2) {
            const int kv0 = t * 64;
#pragma unroll
            for (int nt = 0; nt < 8; nt++)
#pragma unroll
                for (int e = 0; e < 4; e++) {
                    const int key = kv0 + nt * 8 + 2 * (lane & 3) + (e & 1);
                    const int row = qrow + ((e & 2) ? 8 : 0);
                    if (key > row) sacc[nt][e] = -1e30f;
                }
        }

        // ---- online softmax (base-2) ----
#pragma unroll
        for (int hh = 0; hh < 2; hh++) {
            float& mprev = hh ? m1 : m0;
            float& lsum  = hh ? l1 : l0;
            float mx = -1e30f;
#pragma unroll
            for (int nt = 0; nt < 8; nt++)
                mx = fmaxf(mx, fmaxf(sacc[nt][hh*2], sacc[nt][hh*2+1]));
            mx = fmaxf(mx, __shfl_xor_sync(0xffffffffu, mx, 1));
            mx = fmaxf(mx, __shfl_xor_sync(0xffffffffu, mx, 2));
            const float mn = fmaxf(mprev, mx);

            if (__any_sync(0xffffffffu, mn > mprev)) {
                const float alpha = exp2f(mprev - mn);
                lsum *= alpha;
#pragma unroll
                for (int nt = 0; nt < 8; nt++) {
                    oacc[nt][hh*2]   *= alpha;
                    oacc[nt][hh*2+1] *= alpha;
                }
                mprev = mn;
            }

            float ps = 0.f;
#pragma unroll
            for (int nt = 0; nt < 8; nt++) {
                const float p0 = exp2f(sacc[nt][hh*2]   - mprev);
                const float p1 = exp2f(sacc[nt][hh*2+1] - mprev);
                ps += p0 + p1;
                sacc[nt][hh*2]   = p0;
                sacc[nt][hh*2+1] = p1;
            }
            lsum += ps;
        }

        // ---- pack P fp16 into A fragments ----
        uint32_t ap[4][4];
#pragma unroll
        for (int ck = 0; ck < 4; ck++) {
            ap[ck][0] = pkf2(sacc[2*ck][0],   sacc[2*ck][1]);
            ap[ck][1] = pkf2(sacc[2*ck][2],   sacc[2*ck][3]);
            ap[ck][2] = pkf2(sacc[2*ck+1][0], sacc[2*ck+1][1]);
            ap[ck][3] = pkf2(sacc[2*ck+1][2], sacc[2*ck+1][3]);
        }

        // ---- O += P @ V : single pass, f32 acc ----
#pragma unroll
        for (int nt = 0; nt < 8; nt++) {
            const uint32_t va = bu + KVTILE_B + (uint32_t)(lane * RS + nt * 16);
            uint32_t vf[8];
            ldsm_x4t(vf, va);
            ldsm_x4t(vf + 4, va + 32 * RS);
#pragma unroll
            for (int ck = 0; ck < 4; ck++)
                mma_f32(oacc[nt], ap[ck], &vf[ck * 2]);
        }
    }

    // ---- finalize ----
    l0 += __shfl_xor_sync(0xffffffffu, l0, 1);
    l0 += __shfl_xor_sync(0xffffffffu, l0, 2);
    l1 += __shfl_xor_sync(0xffffffffu, l1, 1);
    l1 += __shfl_xor_sync(0xffffffffu, l1, 2);
    const float inv0 = 1.f / l0;
    const float inv1 = 1.f / l1;

#pragma unroll
    for (int nt = 0; nt < 8; nt++) {
        const int d = nt * 8 + 2 * (lane & 3);
#pragma unroll
        for (int hh = 0; hh < 2; hh++) {
            const int row = qrow + hh * 8;
            const float inv = hh ? inv1 : inv0;
            const size_t dst = ((size_t)(b * TT + row)) * CC + h * HD + d;
            *(uint32_t*)(g_ao + dst) = pkf2(oacc[nt][hh*2] * inv,
                                            oacc[nt][hh*2+1] * inv);
        }
    }
}

// ---------------------------------------------------------------------------
extern "C" void kernel_launch(void* const* d_in, const int* in_sizes, int n_in,
                              void* d_out, int out_size)
{
    const float* x  = (const float*)d_in[0];
    const float* Wq = (const float*)d_in[1];
    const float* bq = (const float*)d_in[2];
    const float* Wk = (const float*)d_in[3];
    const float* bk = (const float*)d_in[4];
    const float* Wv = (const float*)d_in[5];
    const float* bv = (const float*)d_in[6];
    const float* Wo = (const float*)d_in[7];
    const float* bo = (const float*)d_in[8];
    float* out = (float*)d_out;

    __half *xs, *q, *k, *v, *ao, *wt;
    cudaGetSymbolAddress((void**)&xs, g_x);
    cudaGetSymbolAddress((void**)&q,  g_q);
    cudaGetSymbolAddress((void**)&k,  g_k);
    cudaGetSymbolAddress((void**)&v,  g_v);
    cudaGetSymbolAddress((void**)&ao, g_ao);
    cudaGetSymbolAddress((void**)&wt, g_wt);

    static bool attr_set = false;
    if (!attr_set) {
        cudaFuncSetAttribute((const void*)mmagemm<0>,
                             cudaFuncAttributeMaxDynamicSharedMemorySize, GEMM_SMEM);
        cudaFuncSetAttribute((const void*)mmagemm<1>,
                             cudaFuncAttributeMaxDynamicSharedMemorySize, GEMM_SMEM);
        cudaFuncSetAttribute((const void*)flash8,
                             cudaFuncAttributeMaxDynamicSharedMemorySize, FL_SMEM);
        attr_set = true;
    }

    // fused prep: 4 weight casts + x cast
    dim3 pgrid(CC / 32, CC / 32, 5);
    prep<<<pgrid, 256>>>(x, Wq, Wk, Wv, Wo, xs, wt);

    // fused QKV projection (N = 3072), 1-pass fp16
    dim3 qkv_grid(3 * CC / 128, MROWS / 128);   // (24, 32)
    mmagemm<1><<<qkv_grid, 256, GEMM_SMEM>>>(xs, wt, bq, bk, bv,
                                             nullptr, q, k, v);

    dim3 att_grid(TT / 128, HH, BB);
    flash8<<<att_grid, 256, FL_SMEM>>>(k, q, v);

    // output projection (N = 1024), 1-pass fp16
    dim3 out_grid(CC / 128, MROWS / 128);       // (8, 32)
    mmagemm<0><<<out_grid, 256, GEMM_SMEM>>>(ao, wt + 3*(size_t)CC*CC,
                                             bo, nullptr, nullptr,
                                             out, nullptr, nullptr, nullptr);
}

// round 17
// speedup vs baseline: 2.8922x; 1.0320x over previous
#include <cuda_runtime.h>
#include <cuda_fp16.h>
#include <stdint.h>
#include <math.h>

// Problem constants
#define BB 2
#define TT 2048
#define CC 1024
#define HH 16
#define HD 64
#define MROWS (BB*TT)

// ---------------------------------------------------------------------------
// Scratch (allocation-free rule: __device__ globals) — all single fp16
// ---------------------------------------------------------------------------
__device__ __half g_x  [MROWS*CC];
__device__ __half g_q  [MROWS*CC];     // Q fp16, pre-scaled by 0.125*log2e
__device__ __half g_k  [MROWS*CC];
__device__ __half g_v  [MROWS*CC];
__device__ __half g_ao [MROWS*CC];
__device__ __half g_wt [4*CC*CC];      // [w][n][k]  (W^T, K-major, fp16)

// ---------------------------------------------------------------------------
// Warp-MMA helpers (base sm_80+ features)
// ---------------------------------------------------------------------------
__device__ __forceinline__ uint32_t s2u(const void* p) {
    uint32_t a;
    asm("{ .reg .u64 t; cvta.to.shared.u64 t, %1; cvt.u32.u64 %0, t; }"
        : "=r"(a) : "l"(p));
    return a;
}
__device__ __forceinline__ void ldsm_x4(uint32_t* r, uint32_t addr) {
    asm volatile("ldmatrix.sync.aligned.m8n8.x4.shared.b16 {%0,%1,%2,%3}, [%4];"
        : "=r"(r[0]), "=r"(r[1]), "=r"(r[2]), "=r"(r[3]) : "r"(addr));
}
__device__ __forceinline__ void ldsm_x4t(uint32_t* r, uint32_t addr) {
    asm volatile("ldmatrix.sync.aligned.m8n8.x4.trans.shared.b16 {%0,%1,%2,%3}, [%4];"
        : "=r"(r[0]), "=r"(r[1]), "=r"(r[2]), "=r"(r[3]) : "r"(addr));
}
__device__ __forceinline__ void mma_f32(float* c, const uint32_t* a, const uint32_t* b) {
    asm volatile(
        "mma.sync.aligned.m16n8k16.row.col.f32.f16.f16.f32 "
        "{%0,%1,%2,%3}, {%4,%5,%6,%7}, {%8,%9}, {%0,%1,%2,%3};"
        : "+f"(c[0]), "+f"(c[1]), "+f"(c[2]), "+f"(c[3])
        : "r"(a[0]), "r"(a[1]), "r"(a[2]), "r"(a[3]), "r"(b[0]), "r"(b[1]));
}
__device__ __forceinline__ void cpa16(uint32_t dst, const void* src) {
    asm volatile("cp.async.cg.shared.global [%0], [%1], 16;" :: "r"(dst), "l"(src));
}
#define CP_COMMIT() asm volatile("cp.async.commit_group;" ::: "memory")
#define CP_WAIT(n)  asm volatile("cp.async.wait_group %0;" :: "n"(n) : "memory")

__device__ __forceinline__ uint32_t pkf2(float a, float b) {
    __half2 t = __floats2half2_rn(a, b);
    return *(uint32_t*)&t;
}

// ---------------------------------------------------------------------------
// Fused prep kernel: z=0..3 -> weight transpose+cast; z=4 -> x cast.
// ---------------------------------------------------------------------------
__global__ __launch_bounds__(256)
void prep(const float* __restrict__ x,
          const float* __restrict__ W0, const float* __restrict__ W1,
          const float* __restrict__ W2, const float* __restrict__ W3,
          __half* __restrict__ xs, __half* __restrict__ wt)
{
    if (blockIdx.z == 4) {
        const int blk = blockIdx.x + blockIdx.y * gridDim.x;
#pragma unroll
        for (int r = 0; r < 4; r++) {
            const int idx = blk * 1024 + r * 256 + threadIdx.x;
            float4 v = ((const float4*)x)[idx];
            uint2 hw = { pkf2(v.x, v.y), pkf2(v.z, v.w) };
            ((uint2*)xs)[idx] = hw;
        }
        return;
    }

    __shared__ float t[32][33];
    const int wsel = blockIdx.z;
    const float* W = (wsel == 0) ? W0 : (wsel == 1) ? W1 : (wsel == 2) ? W2 : W3;
    __half* th = wt + (size_t)wsel * CC * CC;

    const int n0 = blockIdx.x * 32;
    const int k0 = blockIdx.y * 32;
    const int tx = threadIdx.x & 31;
    const int ty = threadIdx.x >> 5;
#pragma unroll
    for (int r = 0; r < 4; r++) {
        const int row = ty + r * 8;
        t[row][tx] = W[(size_t)(k0 + row) * CC + n0 + tx];
    }
    __syncthreads();
#pragma unroll
    for (int r = 0; r < 4; r++) {
        const int row = ty + r * 8;
        th[(size_t)(n0 + row) * CC + k0 + tx] = __float2half_rn(t[tx][row]);
    }
}

// ---------------------------------------------------------------------------
// mma.sync fp16 GEMM (128x128 CTA tile, f32-acc), single pass, KC=32,
// 4-stage cp.async pipeline. (unchanged from R16 except .cg fills)
// ---------------------------------------------------------------------------
#define KC 32
#define NCHUNK (CC/KC)               // 32
#define TS2 80
#define TILE2_B (128*TS2)            // 10240
#define BUF2_B  (2*TILE2_B)          // 20480
#define GEMM_SMEM (4*BUF2_B)         // 81920
#define QSCALE 0.1803368801111f      // 0.125 * log2(e)

template<int MODE>
__global__ __launch_bounds__(256, 2)
void mmagemm(const __half* __restrict__ Ah,
             const __half* __restrict__ Wt,
             const float* __restrict__ b0, const float* __restrict__ b1,
             const float* __restrict__ b2,
             float* __restrict__ Y,
             __half* __restrict__ Yq, __half* __restrict__ Yk,
             __half* __restrict__ Yv)
{
    extern __shared__ char dsm[];
    const uint32_t sb = s2u(dsm);

    const int tid = threadIdx.x;
    const int lane = tid & 31;
    const int wid = tid >> 5;
    const int warp_m = wid & 1;
    const int warp_n = wid >> 1;
    const int bm = blockIdx.y * 128;
    const int bn = blockIdx.x * 128;

    const int which = (MODE == 1) ? (bn >> 10) : 0;
    const int nw = bn & (CC - 1);
    const __half* Bm = Wt + (size_t)which * CC * CC;
    const float* bias = (MODE == 0) ? b0 : (which == 0) ? b0 : (which == 1) ? b1 : b2;
    const float scale = (MODE == 1 && which == 0) ? QSCALE : 1.0f;

    float acc[4][4][4];
#pragma unroll
    for (int i = 0; i < 4; i++)
#pragma unroll
        for (int j = 0; j < 4; j++)
#pragma unroll
            for (int q = 0; q < 4; q++) acc[i][j][q] = 0.f;

    auto issue = [&](int c) {
        const int k0 = c * KC;
        const uint32_t bu = sb + (c & 3) * BUF2_B;
#pragma unroll
        for (int i = 0; i < 2; i++) {
#pragma unroll
            for (int o = 0; o < 2; o++) {
                const int j = o * 256 + tid;
                const int row = j >> 2;
                const int seg = j & 3;
                const __half* s = (i == 0) ? Ah : Bm;
                const int rb = (i == 0) ? bm : nw;
                cpa16(bu + i * TILE2_B + row * TS2 + seg * 16,
                      s + (size_t)(rb + row) * CC + k0 + seg * 8);
            }
        }
        CP_COMMIT();
    };

    issue(0); issue(1); issue(2);

    const uint32_t a_off = (uint32_t)((warp_m * 64 + (lane & 15)) * TS2
                                      + (lane >> 4) * 16);
    const uint32_t b_off = (uint32_t)((warp_n * 32 + ((lane >> 4) * 8) + (lane & 7)) * TS2
                                      + ((lane >> 3) & 1) * 16);

    for (int c = 0; c < NCHUNK; c++) {
        const int rem = NCHUNK - 1 - c;
        if (rem >= 2)      CP_WAIT(2);
        else if (rem == 1) CP_WAIT(1);
        else               CP_WAIT(0);
        __syncthreads();
        if (c + 3 < NCHUNK) issue(c + 3);

        const uint32_t bu = sb + (c & 3) * BUF2_B;

#pragma unroll
        for (int kk = 0; kk < 2; kk++) {
            const uint32_t koff = (uint32_t)(kk * 32);
            uint32_t af[4][4];
            uint32_t bf[2][4];
#pragma unroll
            for (int p = 0; p < 2; p++)
                ldsm_x4(bf[p], bu + TILE2_B + b_off + koff
                               + (uint32_t)(p * 16 * TS2));
#pragma unroll
            for (int mt = 0; mt < 4; mt++)
                ldsm_x4(af[mt], bu + a_off + koff + (uint32_t)(mt * 16 * TS2));
#pragma unroll
            for (int mt = 0; mt < 4; mt++)
#pragma unroll
                for (int nt = 0; nt < 4; nt++)
                    mma_f32(acc[mt][nt], af[mt], &bf[nt >> 1][(nt & 1) * 2]);
        }
    }

#pragma unroll
    for (int mt = 0; mt < 4; mt++) {
#pragma unroll
        for (int nt = 0; nt < 4; nt++) {
            const int m0 = bm + warp_m * 64 + mt * 16 + (lane >> 2);
            const int nn = nw + warp_n * 32 + nt * 8 + 2 * (lane & 3);
            const float bb0 = __ldg(bias + nn);
            const float bb1 = __ldg(bias + nn + 1);
#pragma unroll
            for (int half = 0; half < 2; half++) {
                const int m = m0 + half * 8;
                const int bb = m >> 11;
                const int tt = m & (TT - 1);
                const float v0 = (acc[mt][nt][half * 2 + 0] + bb0) * scale;
                const float v1 = (acc[mt][nt][half * 2 + 1] + bb1) * scale;
                if (MODE == 0) {
                    float2 r; r.x = v0; r.y = v1;
                    *(float2*)(Y + (size_t)m * CC + nn) = r;
                } else {
                    const int h = nn >> 6;
                    const int d = nn & (HD - 1);
                    const size_t dst = (((size_t)bb * HH + h) * TT + tt) * HD + d;
                    __half* dp = (which == 0) ? Yq : (which == 1) ? Yk : Yv;
                    *(uint32_t*)(dp + dst) = pkf2(v0, v1);
                }
            }
        }
    }
}

// ---------------------------------------------------------------------------
// flash9: FA2 mma.sync causal attention, base-2 softmax, low-register
// (<=128 regs -> 2 CTAs/SM). 64-key KV tiles processed as 2x32-key halves.
//  - per-half early-out on fully-masked work
//  - reversed qt order (heavy CTAs first)
//  - warp-uniform rescale skip
// CTA: 128 q-rows, 8 warps x 16 rows. 4-stage KV pipeline, prefetch 3.
// ---------------------------------------------------------------------------
#define RS 144
#define QTILE_B (128*RS)                 // 18432
#define KVTILE_B (64*RS)                 // 9216
#define KVBUF_B (2*KVTILE_B)             // 18432 (K, V)
#define FL_SMEM (QTILE_B + 4*KVBUF_B)    // 92160

__global__ __launch_bounds__(256, 2)
void flash9(const __half* __restrict__ K_, const __half* __restrict__ Q,
            const __half* __restrict__ V_)
{
    extern __shared__ char sm[];
    const uint32_t sb = s2u(sm);
    const uint32_t kvb = sb + QTILE_B;

    const int tid = threadIdx.x;
    const int lane = tid & 31;
    const int wid = tid >> 5;
    const int qt = (gridDim.x - 1) - blockIdx.x;   // heavy CTAs first
    const int h  = blockIdx.y;
    const int b  = blockIdx.z;
    const size_t head = ((size_t)b * HH + h) * TT * HD;

#pragma unroll
    for (int i = 0; i < 4; i++) {
        const int idx = i * 256 + tid;
        const int row = (idx >> 3) & 127;
        const int seg = idx & 7;
        cpa16(sb + row * RS + seg * 16,
              Q + head + (size_t)(qt * 128 + row) * HD + seg * 8);
    }
    CP_COMMIT();

    auto issue_kv = [&](int t) {
        const int kv0 = t * 64;
        const uint32_t bu = kvb + (t & 3) * KVBUF_B;
#pragma unroll
        for (int i = 0; i < 4; i++) {
            const int idx = i * 256 + tid;
            const int tile = idx >> 9;
            const int row = (idx >> 3) & 63;
            const int seg = idx & 7;
            const __half* src = (tile == 0) ? K_ : V_;
            cpa16(bu + tile * KVTILE_B + row * RS + seg * 16,
                  src + head + (size_t)(kv0 + row) * HD + seg * 8);
        }
        CP_COMMIT();
    };

    const int ntiles = (qt + 1) * 2;
    issue_kv(0);
    issue_kv(1);
    if (2 < ntiles) issue_kv(2);

    if (2 < ntiles) CP_WAIT(3);
    else            CP_WAIT(2);
    __syncthreads();

    uint32_t qf[4][4];
    {
        const uint32_t qaddr = sb + (uint32_t)((wid * 16 + (lane & 15)) * RS
                                               + (lane >> 4) * 16);
#pragma unroll
        for (int ck = 0; ck < 4; ck++)
            ldsm_x4(qf[ck], qaddr + ck * 32);
    }

    float m0 = -1e30f, m1 = -1e30f, l0 = 0.f, l1 = 0.f;
    float oacc[8][4];
#pragma unroll
    for (int nt = 0; nt < 8; nt++)
#pragma unroll
        for (int e = 0; e < 4; e++) oacc[nt][e] = 0.f;

    const int wrow0 = qt * 128 + wid * 16;     // warp's first q row
    const int qrow = wrow0 + (lane >> 2);

    for (int t = 0; t < ntiles; t++) {
        const int rem = ntiles - 1 - t;
        if (rem >= 2)      CP_WAIT(2);
        else if (rem == 1) CP_WAIT(1);
        else               CP_WAIT(0);
        __syncthreads();
        if (t + 3 < ntiles) issue_kv(t + 3);

        const uint32_t bu = kvb + (t & 3) * KVBUF_B;

#pragma unroll 1
        for (int hf = 0; hf < 2; hf++) {       // 32-key halves
            const int kv0h = t * 64 + hf * 32;
            if (kv0h > wrow0 + 15) continue;   // fully masked for this warp

            const uint32_t buk = bu + (uint32_t)(hf * 32 * RS);

            // ---- S(log2) = Q @ K^T over 32 keys, f32 acc ----
            float sacc[4][4];
#pragma unroll
            for (int nt = 0; nt < 4; nt++)
#pragma unroll
                for (int e = 0; e < 4; e++) sacc[nt][e] = 0.f;

#pragma unroll
            for (int nt = 0; nt < 4; nt++) {
                const uint32_t ka = buk + (uint32_t)((nt * 8 + (lane & 7)) * RS
                                                     + (lane >> 3) * 16);
                uint32_t kf[8];
                ldsm_x4(kf, ka);
                ldsm_x4(kf + 4, ka + 64);
#pragma unroll
                for (int ck = 0; ck < 4; ck++)
                    mma_f32(sacc[nt], qf[ck], &kf[ck * 2]);
            }

            // ---- causal mask (partially masked halves only) ----
            if (kv0h + 31 > wrow0) {
#pragma unroll
                for (int nt = 0; nt < 4; nt++)
#pragma unroll
                    for (int e = 0; e < 4; e++) {
                        const int key = kv0h + nt * 8 + 2 * (lane & 3) + (e & 1);
                        const int row = qrow + ((e & 2) ? 8 : 0);
                        if (key > row) sacc[nt][e] = -1e30f;
                    }
            }

            // ---- online softmax (base-2) ----
#pragma unroll
            for (int hh = 0; hh < 2; hh++) {
                float& mprev = hh ? m1 : m0;
                float& lsum  = hh ? l1 : l0;
                float mx = -1e30f;
#pragma unroll
                for (int nt = 0; nt < 4; nt++)
                    mx = fmaxf(mx, fmaxf(sacc[nt][hh*2], sacc[nt][hh*2+1]));
                mx = fmaxf(mx, __shfl_xor_sync(0xffffffffu, mx, 1));
                mx = fmaxf(mx, __shfl_xor_sync(0xffffffffu, mx, 2));
                const float mn = fmaxf(mprev, mx);

                if (__any_sync(0xffffffffu, mn > mprev)) {
                    const float alpha = exp2f(mprev - mn);
                    lsum *= alpha;
#pragma unroll
                    for (int nt = 0; nt < 8; nt++) {
                        oacc[nt][hh*2]   *= alpha;
                        oacc[nt][hh*2+1] *= alpha;
                    }
                    mprev = mn;
                }

                float ps = 0.f;
#pragma unroll
                for (int nt = 0; nt < 4; nt++) {
                    const float p0 = exp2f(sacc[nt][hh*2]   - mprev);
                    const float p1 = exp2f(sacc[nt][hh*2+1] - mprev);
                    ps += p0 + p1;
                    sacc[nt][hh*2]   = p0;
                    sacc[nt][hh*2+1] = p1;
                }
                lsum += ps;
            }

            // ---- pack P fp16 (2 k16 fragments) ----
            uint32_t ap[2][4];
#pragma unroll
            for (int ck = 0; ck < 2; ck++) {
                ap[ck][0] = pkf2(sacc[2*ck][0],   sacc[2*ck][1]);
                ap[ck][1] = pkf2(sacc[2*ck][2],   sacc[2*ck][3]);
                ap[ck][2] = pkf2(sacc[2*ck+1][0], sacc[2*ck+1][1]);
                ap[ck][3] = pkf2(sacc[2*ck+1][2], sacc[2*ck+1][3]);
            }

            // ---- O += P @ V over 32 keys ----
#pragma unroll
            for (int nt = 0; nt < 8; nt++) {
                const uint32_t va = bu + KVTILE_B
                                  + (uint32_t)((hf * 32 + lane) * RS + nt * 16);
                uint32_t vf[4];
                ldsm_x4t(vf, va);
#pragma unroll
                for (int ck = 0; ck < 2; ck++)
                    mma_f32(oacc[nt], ap[ck], &vf[ck * 2]);
            }
        }
    }

    // ---- finalize ----
    l0 += __shfl_xor_sync(0xffffffffu, l0, 1);
    l0 += __shfl_xor_sync(0xffffffffu, l0, 2);
    l1 += __shfl_xor_sync(0xffffffffu, l1, 1);
    l1 += __shfl_xor_sync(0xffffffffu, l1, 2);
    const float inv0 = 1.f / l0;
    const float inv1 = 1.f / l1;

#pragma unroll
    for (int nt = 0; nt < 8; nt++) {
        const int d = nt * 8 + 2 * (lane & 3);
#pragma unroll
        for (int hh = 0; hh < 2; hh++) {
            const int row = qrow + hh * 8;
            const float inv = hh ? inv1 : inv0;
            const size_t dst = ((size_t)(b * TT + row)) * CC + h * HD + d;
            *(uint32_t*)(g_ao + dst) = pkf2(oacc[nt][hh*2] * inv,
                                            oacc[nt][hh*2+1] * inv);
        }
    }
}

// ---------------------------------------------------------------------------
extern "C" void kernel_launch(void* const* d_in, const int* in_sizes, int n_in,
                              void* d_out, int out_size)
{
    const float* x  = (const float*)d_in[0];
    const float* Wq = (const float*)d_in[1];
    const float* bq = (const float*)d_in[2];
    const float* Wk = (const float*)d_in[3];
    const float* bk = (const float*)d_in[4];
    const float* Wv = (const float*)d_in[5];
    const float* bv = (const float*)d_in[6];
    const float* Wo = (const float*)d_in[7];
    const float* bo = (const float*)d_in[8];
    float* out = (float*)d_out;

    __half *xs, *q, *k, *v, *ao, *wt;
    cudaGetSymbolAddress((void**)&xs, g_x);
    cudaGetSymbolAddress((void**)&q,  g_q);
    cudaGetSymbolAddress((void**)&k,  g_k);
    cudaGetSymbolAddress((void**)&v,  g_v);
    cudaGetSymbolAddress((void**)&ao, g_ao);
    cudaGetSymbolAddress((void**)&wt, g_wt);

    static bool attr_set = false;
    if (!attr_set) {
        cudaFuncSetAttribute((const void*)mmagemm<0>,
                             cudaFuncAttributeMaxDynamicSharedMemorySize, GEMM_SMEM);
        cudaFuncSetAttribute((const void*)mmagemm<1>,
                             cudaFuncAttributeMaxDynamicSharedMemorySize, GEMM_SMEM);
        cudaFuncSetAttribute((const void*)flash9,
                             cudaFuncAttributeMaxDynamicSharedMemorySize, FL_SMEM);
        attr_set = true;
    }

    // fused prep: 4 weight casts + x cast
    dim3 pgrid(CC / 32, CC / 32, 5);
    prep<<<pgrid, 256>>>(x, Wq, Wk, Wv, Wo, xs, wt);

    // fused QKV projection (N = 3072), 1-pass fp16
    dim3 qkv_grid(3 * CC / 128, MROWS / 128);   // (24, 32)
    mmagemm<1><<<qkv_grid, 256, GEMM_SMEM>>>(xs, wt, bq, bk, bv,
                                             nullptr, q, k, v);

    dim3 att_grid(TT / 128, HH, BB);
    flash9<<<att_grid, 256, FL_SMEM>>>(k, q, v);

    // output projection (N = 1024), 1-pass fp16
    dim3 out_grid(CC / 128, MROWS / 128);       // (8, 32)
    mmagemm<0><<<out_grid, 256, GEMM_SMEM>>>(ao, wt + 3*(size_t)CC*CC,
                                             bo, nullptr, nullptr,
                                             out, nullptr, nullptr, nullptr);
}